// round 9
// baseline (speedup 1.0000x reference)
#include <cuda_runtime.h>
#include <cstdint>

#define D 128
#define S 12
#define ITEMS_PER_TILE 16
#define MTILE 192            // 6 warps x 32 rows (2 m16 tiles each)
#define NWARPS 6
#define NTHREADS 192
#define KSTEPS 8             // K=128, 16 per bf16 mma
#define FLDF 136             // feat row stride in bf16 elems (272B) -> conflict-free A loads

// ---- scratch (allocation-free rule) ----
__device__ float g_agg_a[3200  * 128];
__device__ float g_agg_b[38400 * 128];
__device__ float g_agg_c[3200  * 128];

// SMEM: feat bf16[192][136] + btab[8][8][32]u4 + it f32[16][128] + w1b+w2s + nbw+lgs+alps
#define FEAT_BYTES (MTILE * FLDF * 2)          // 52224
#define BTAB_BYTES (KSTEPS * 8 * 32 * 16)      // 32768
#define SMEM_BYTES (FEAT_BYTES + BTAB_BYTES + ITEMS_PER_TILE * D * 4 + 256 * 4 + 3 * MTILE * 4)

__device__ __forceinline__ uint32_t bf16x2(float lo, float hi) {
    uint32_t r;
    asm("cvt.rn.bf16x2.f32 %0, %1, %2;" : "=r"(r) : "f"(hi), "f"(lo));
    return r;
}
__device__ __forceinline__ void mma_bf16(float* d, uint32_t a0, uint32_t a1,
                                         uint32_t a2, uint32_t a3,
                                         uint32_t b0, uint32_t b1) {
    asm volatile(
        "mma.sync.aligned.m16n8k16.row.col.f32.bf16.bf16.f32 "
        "{%0,%1,%2,%3}, {%4,%5,%6,%7}, {%8,%9}, {%0,%1,%2,%3};"
        : "+f"(d[0]), "+f"(d[1]), "+f"(d[2]), "+f"(d[3])
        : "r"(a0), "r"(a1), "r"(a2), "r"(a3), "r"(b0), "r"(b1));
}
__device__ __forceinline__ float lrelu(float x) { return x > 0.f ? x : 0.2f * x; }

// Fused aggregate. Tiles divide exactly (3200%16==0, 38400%16==0): no guards.
__global__ __launch_bounds__(NTHREADS, 1) void fused_agg_kernel(
    const float* __restrict__ item, const float* __restrict__ nbh,
    const float* __restrict__ nbw,  const float* __restrict__ w1,
    const float* __restrict__ w2,   float* __restrict__ out,
    int ntiles)
{
    extern __shared__ char smraw[];
    uint16_t* feat = (uint16_t*)smraw;                    // [192][136] bf16
    uint4*    btab = (uint4*)(smraw + FEAT_BYTES);        // [8][8][32]
    float*    its  = (float*)(smraw + FEAT_BYTES + BTAB_BYTES);  // [16][128]
    float*    w1b  = its + ITEMS_PER_TILE * D;            // [128]
    float*    w2s  = w1b + 128;                           // [128]
    float*    nbws = w2s + 128;                           // [192]
    float*    lgs  = nbws + MTILE;                        // [192]
    float*    alps = lgs + MTILE;                         // [192]

    const int tid  = threadIdx.x;
    const int lane = tid & 31;
    const int warp = tid >> 5;
    const int c = lane & 3;
    const int g = lane >> 2;

    // ---- one-time: btab (uint4: j=2p and j=2p+1 fragments), bias row, w2 ----
    for (int idx = tid; idx < KSTEPS * 8 * 32; idx += NTHREADS) {
        const int t  = idx & 31;
        const int p  = (idx >> 5) & 7;
        const int ks = idx >> 8;
        const int tc = t & 3, tg = t >> 2;
        const int k0 = ks * 16 + 2 * tc;
        const int n0 = (2 * p) * 8 + tg;
        const int n1 = (2 * p + 1) * 8 + tg;
        uint4 v;
        v.x = bf16x2(w1[k0 * D + n0],       w1[(k0 + 1) * D + n0]);
        v.y = bf16x2(w1[(k0 + 8) * D + n0], w1[(k0 + 9) * D + n0]);
        v.z = bf16x2(w1[k0 * D + n1],       w1[(k0 + 1) * D + n1]);
        v.w = bf16x2(w1[(k0 + 8) * D + n1], w1[(k0 + 9) * D + n1]);
        btab[idx] = v;
    }
    if (tid < D) { w1b[tid] = w1[D * D + tid]; w2s[tid] = w2[tid]; }

    for (int tile = blockIdx.x; tile < ntiles; tile += gridDim.x) {
        const int rowbase  = tile * MTILE;
        const int itembase = tile * ITEMS_PER_TILE;

        // ---- stage item rows + nbw ----
        for (int idx = tid; idx < ITEMS_PER_TILE * 32; idx += NTHREADS)
            ((float4*)its)[idx] = ((const float4*)item)[(size_t)itembase * 32 + idx];
        if (tid < MTILE / 4)
            *(float4*)&nbws[tid * 4] = ((const float4*)nbw)[(size_t)rowbase / 4 + tid];
        __syncthreads();

        // ---- build bf16 feat tile: feat[r][k] = bf16(nbh[R][k] * item[R/12][k]) ----
        #pragma unroll
        for (int i = 0; i < (MTILE * 32) / NTHREADS; i++) {   // 32 iters
            const int idx = tid + i * NTHREADS;
            const int r = idx >> 5, l4 = idx & 31;
            float4 a = __ldg((const float4*)nbh + (size_t)(rowbase + r) * 32 + l4);
            float4 b = *(const float4*)&its[((unsigned)r / 12u) * D + l4 * 4];
            uint2 pk;
            pk.x = bf16x2(a.x * b.x, a.y * b.y);
            pk.y = bf16x2(a.z * b.z, a.w * b.w);
            *(uint2*)&feat[r * FLDF + l4 * 4] = pk;
        }
        __syncthreads();

        // ---- mainloop: 2 m16 tiles per warp, N=128, bf16 k16 ----
        float acc0[16][4], acc1[16][4];
        #pragma unroll
        for (int j = 0; j < 16; j++)
            #pragma unroll
            for (int q = 0; q < 4; q++) { acc0[j][q] = 0.f; acc1[j][q] = 0.f; }

        const int m0 = warp * 32 + g;        // rows m0, m0+8 (tile A), m0+16, m0+24 (tile B)
        #pragma unroll 1
        for (int ks = 0; ks < KSTEPS; ks++) {
            const int k0 = ks * 16 + 2 * c;
            uint32_t a00 = *(const uint32_t*)&feat[m0 * FLDF + k0];
            uint32_t a01 = *(const uint32_t*)&feat[(m0 + 8) * FLDF + k0];
            uint32_t a02 = *(const uint32_t*)&feat[m0 * FLDF + k0 + 8];
            uint32_t a03 = *(const uint32_t*)&feat[(m0 + 8) * FLDF + k0 + 8];
            uint32_t a10 = *(const uint32_t*)&feat[(m0 + 16) * FLDF + k0];
            uint32_t a11 = *(const uint32_t*)&feat[(m0 + 24) * FLDF + k0];
            uint32_t a12 = *(const uint32_t*)&feat[(m0 + 16) * FLDF + k0 + 8];
            uint32_t a13 = *(const uint32_t*)&feat[(m0 + 24) * FLDF + k0 + 8];
            const uint4* bks = &btab[ks * 8 * 32];
            #pragma unroll
            for (int p = 0; p < 8; p++) {
                uint4 b = bks[p * 32 + lane];
                mma_bf16(acc0[2 * p],     a00, a01, a02, a03, b.x, b.y);
                mma_bf16(acc0[2 * p + 1], a00, a01, a02, a03, b.z, b.w);
                mma_bf16(acc1[2 * p],     a10, a11, a12, a13, b.x, b.y);
                mma_bf16(acc1[2 * p + 1], a10, a11, a12, a13, b.z, b.w);
            }
        }

        // ---- logits: bias, lrelu, dot w2, reduce over c ----
        #pragma unroll
        for (int half = 0; half < 2; half++) {
            float (*acc)[4] = half ? acc1 : acc0;
            const int r0 = warp * 32 + half * 16 + g;
            const int r1 = r0 + 8;
            const float nbw0 = nbws[r0];
            const float nbw1 = nbws[r1];
            float l0 = 0.f, l1 = 0.f;
            #pragma unroll
            for (int j = 0; j < 16; j++) {
                float2 wb = *(const float2*)&w1b[j * 8 + 2 * c];
                float2 wv = *(const float2*)&w2s[j * 8 + 2 * c];
                l0 = fmaf(lrelu(fmaf(nbw0, wb.x, acc[j][0])), wv.x, l0);
                l0 = fmaf(lrelu(fmaf(nbw0, wb.y, acc[j][1])), wv.y, l0);
                l1 = fmaf(lrelu(fmaf(nbw1, wb.x, acc[j][2])), wv.x, l1);
                l1 = fmaf(lrelu(fmaf(nbw1, wb.y, acc[j][3])), wv.y, l1);
            }
            l0 += __shfl_xor_sync(0xffffffffu, l0, 1);
            l0 += __shfl_xor_sync(0xffffffffu, l0, 2);
            l1 += __shfl_xor_sync(0xffffffffu, l1, 1);
            l1 += __shfl_xor_sync(0xffffffffu, l1, 2);
            if (c == 0) { lgs[r0] = l0; lgs[r1] = l1; }
        }
        __syncthreads();

        // ---- softmax per item ----
        if (tid < ITEMS_PER_TILE) {
            const int base = tid * S;
            float m = lgs[base];
            #pragma unroll
            for (int s = 1; s < S; s++) m = fmaxf(m, lgs[base + s]);
            float e[S]; float sum = 0.f;
            #pragma unroll
            for (int s = 0; s < S; s++) { e[s] = __expf(lgs[base + s] - m); sum += e[s]; }
            const float inv = 1.f / sum;
            #pragma unroll
            for (int s = 0; s < S; s++) alps[base + s] = e[s] * inv;
        }
        __syncthreads();

        // ---- weighted neighbor sum: re-read nbh (L2-hot, just streamed) ----
        for (int idx = tid; idx < ITEMS_PER_TILE * 32; idx += NTHREADS) {
            const int i = idx >> 5, l4 = idx & 31;
            const float* al = &alps[i * S];
            const float4* nbp = (const float4*)nbh + (size_t)(rowbase + i * S) * 32 + l4;
            float4 o = make_float4(0.f, 0.f, 0.f, 0.f);
            #pragma unroll
            for (int s = 0; s < S; s++) {
                float4 v = __ldg(nbp + (size_t)s * 32);
                const float a = al[s];
                o.x = fmaf(a, v.x, o.x); o.y = fmaf(a, v.y, o.y);
                o.z = fmaf(a, v.z, o.z); o.w = fmaf(a, v.w, o.w);
            }
            *(float4*)&out[(size_t)(itembase + i) * D + l4 * 4] = o;
        }
        __syncthreads();   // smem reused next tile
    }
}

// ---- final gating: 4 items per block, grid 800 ----
#define FMA2(acc, a, b) \
    asm("fma.rn.f32x2 %0, %1, %2, %0;" : "+l"(acc) : "l"(a), "l"(b))
__device__ __forceinline__ unsigned long long pack_f32(float lo, float hi) {
    unsigned long long p;
    asm("mov.b64 %0, {%1, %2};" : "=l"(p) : "r"(__float_as_uint(lo)), "r"(__float_as_uint(hi)));
    return p;
}
__device__ __forceinline__ void unpack_f32(unsigned long long p, float& lo, float& hi) {
    asm("mov.b64 {%0, %1}, %2;" : "=f"(lo), "=f"(hi) : "l"(p));
}

__global__ __launch_bounds__(128) void final_kernel(
    const float* __restrict__ hidden, const float* __restrict__ agg_a,
    const float* __restrict__ agg_c,  const float* __restrict__ w3,
    const float* __restrict__ w4,     const float* __restrict__ sv,
    float* __restrict__ out)
{
    const int nbase = blockIdx.x * 4;
    const int t = threadIdx.x;
    __shared__ unsigned long long sh_hg[4][D];

    const float s0 = sv[0], s1 = sv[1];
    float h[4], g[4];
    #pragma unroll
    for (int i = 0; i < 4; i++) {
        const size_t off = (size_t)(nbase + i) * D + t;
        h[i] = hidden[off];
        g[i] = s0 * agg_a[off] + s1 * agg_c[off];
        sh_hg[i][t] = pack_f32(h[i], g[i]);
    }
    __syncthreads();

    unsigned long long acc[4] = {0ULL, 0ULL, 0ULL, 0ULL};
    const float* w3c = w3 + t;
    const float* w4c = w4 + t;
    #pragma unroll 4
    for (int k = 0; k < D; k++) {
        unsigned long long wp = pack_f32(__ldg(&w3c[k * D]), __ldg(&w4c[k * D]));
        #pragma unroll
        for (int i = 0; i < 4; i++) FMA2(acc[i], sh_hg[i][k], wp);
    }
    #pragma unroll
    for (int i = 0; i < 4; i++) {
        float a0, a1;
        unpack_f32(acc[i], a0, a1);
        const float wgt = 1.f / (1.f + __expf(-(a0 + a1)));
        out[(size_t)(nbase + i) * D + t] = (1.f - wgt) * h[i] + wgt * g[i];
    }
}

extern "C" void kernel_launch(void* const* d_in, const int* in_sizes, int n_in,
                              void* d_out, int out_size)
{
    const float* hidden = (const float*)d_in[0];
    const float* nh1    = (const float*)d_in[1];
    const float* nh2    = (const float*)d_in[2];
    const float* nw0    = (const float*)d_in[3];
    const float* nw1    = (const float*)d_in[4];
    const float* w1     = (const float*)d_in[5];
    const float* w2     = (const float*)d_in[6];
    const float* w3     = (const float*)d_in[7];
    const float* w4     = (const float*)d_in[8];
    const float* sv     = (const float*)d_in[9];
    float* out = (float*)d_out;

    float *agg_a, *agg_b, *agg_c;
    cudaGetSymbolAddress((void**)&agg_a, g_agg_a);
    cudaGetSymbolAddress((void**)&agg_b, g_agg_b);
    cudaGetSymbolAddress((void**)&agg_c, g_agg_c);

    cudaFuncSetAttribute(fused_agg_kernel,
                         cudaFuncAttributeMaxDynamicSharedMemorySize, SMEM_BYTES);

    const int GP = 148;
    const int T0 = 3200  / ITEMS_PER_TILE;   // 200 tiles (exact)
    const int T1 = 38400 / ITEMS_PER_TILE;   // 2400 tiles (exact)

    // hop 1
    fused_agg_kernel<<<GP, NTHREADS, SMEM_BYTES>>>(hidden, nh1, nw0, w1, w2, agg_a, T0);
    fused_agg_kernel<<<GP, NTHREADS, SMEM_BYTES>>>(nh1,    nh2, nw1, w1, w2, agg_b, T1);
    // hop 2
    fused_agg_kernel<<<GP, NTHREADS, SMEM_BYTES>>>(agg_a,  agg_b, nw0, w1, w2, agg_c, T0);
    // gate
    final_kernel<<<800, 128>>>(hidden, agg_a, agg_c, w3, w4, sv, out);
}

// round 10
// speedup vs baseline: 1.8180x; 1.8180x over previous
#include <cuda_runtime.h>
#include <cstdint>

#define D 128
#define S 12
#define ITEMS_PER_TILE 8
#define MTILE 96             // 6 warps x 16 rows (one m16 tile each)
#define NWARPS 6
#define NTHREADS 192
#define KSTEPS 8             // K=128, 16 per bf16 mma
#define FLDF 136             // bf16 feat row stride (elems) -> conflict-free A loads

// ---- scratch (allocation-free rule) ----
__device__ float g_agg_a[3200  * 128];
__device__ float g_agg_b[38400 * 128];
__device__ float g_agg_c[3200  * 128];

#define NBSZ   (MTILE * D)              // 12288 floats per nb buffer
#define ITSZ   (ITEMS_PER_TILE * D)     // 1024 floats per item buffer
#define FEAT_BYTES (MTILE * FLDF * 2)   // 26112
#define BTAB_BYTES (KSTEPS * 8 * 32 * 16) // 32768
#define SMEM_BYTES (2 * NBSZ * 4 + 2 * ITSZ * 4 + FEAT_BYTES + BTAB_BYTES \
                    + 256 * 4 + 2 * MTILE * 4 + 2 * MTILE * 4)

__device__ __forceinline__ uint32_t bf16x2(float lo, float hi) {
    uint32_t r;
    asm("cvt.rn.bf16x2.f32 %0, %1, %2;" : "=r"(r) : "f"(hi), "f"(lo));
    return r;
}
__device__ __forceinline__ void mma_bf16(float* d, uint32_t a0, uint32_t a1,
                                         uint32_t a2, uint32_t a3,
                                         uint32_t b0, uint32_t b1) {
    asm volatile(
        "mma.sync.aligned.m16n8k16.row.col.f32.bf16.bf16.f32 "
        "{%0,%1,%2,%3}, {%4,%5,%6,%7}, {%8,%9}, {%0,%1,%2,%3};"
        : "+f"(d[0]), "+f"(d[1]), "+f"(d[2]), "+f"(d[3])
        : "r"(a0), "r"(a1), "r"(a2), "r"(a3), "r"(b0), "r"(b1));
}
__device__ __forceinline__ float lrelu(float x) { return x > 0.f ? x : 0.2f * x; }

__device__ __forceinline__ void cp16(uint32_t smem_dst, const void* gsrc) {
    asm volatile("cp.async.cg.shared.global [%0], [%1], 16;" :: "r"(smem_dst), "l"(gsrc));
}
__device__ __forceinline__ void cp_commit() {
    asm volatile("cp.async.commit_group;");
}
__device__ __forceinline__ void cp_wait1() {
    asm volatile("cp.async.wait_group 1;" ::: "memory");
}
__device__ __forceinline__ uint32_t smem_u32(const void* p) {
    return (uint32_t)__cvta_generic_to_shared(p);
}

// Fused aggregate: cp.async double-buffered tiles; bf16 feat; tensor-core GEMM;
// softmax + weighted sum from resident fp32 SMEM. Exact tiling (no guards).
__global__ __launch_bounds__(NTHREADS, 1) void fused_agg_kernel(
    const float* __restrict__ item, const float* __restrict__ nbh,
    const float* __restrict__ nbw,  const float* __restrict__ w1,
    const float* __restrict__ w2,   float* __restrict__ out,
    int ntiles)
{
    extern __shared__ char smraw[];
    float*    nbbuf  = (float*)smraw;                         // [2][96*128]
    float*    itbuf  = nbbuf + 2 * NBSZ;                      // [2][8*128]
    uint16_t* feat   = (uint16_t*)(itbuf + 2 * ITSZ);         // [96][136] bf16
    uint4*    btab   = (uint4*)((char*)feat + FEAT_BYTES);    // [8][8][32]
    float*    w1b    = (float*)((char*)btab + BTAB_BYTES);    // [128]
    float*    w2s    = w1b + 128;                             // [128]
    float*    nbwbuf = w2s + 128;                             // [2][96]
    float*    lgs    = nbwbuf + 2 * MTILE;                    // [96]
    float*    alps   = lgs + MTILE;                           // [96]

    const int tid  = threadIdx.x;
    const int lane = tid & 31;
    const int warp = tid >> 5;
    const int c = lane & 3;
    const int g = lane >> 2;
    const int wrow = warp * 16;

    // ---- one-time: btab uint4 (two adjacent n-tiles per entry), bias row, w2 ----
    for (int idx = tid; idx < KSTEPS * 8 * 32; idx += NTHREADS) {
        const int t  = idx & 31;
        const int p  = (idx >> 5) & 7;
        const int ks = idx >> 8;
        const int tc = t & 3, tg = t >> 2;
        const int k0 = ks * 16 + 2 * tc;
        const int n0 = (2 * p) * 8 + tg;
        const int n1 = (2 * p + 1) * 8 + tg;
        uint4 v;
        v.x = bf16x2(w1[k0 * D + n0],       w1[(k0 + 1) * D + n0]);
        v.y = bf16x2(w1[(k0 + 8) * D + n0], w1[(k0 + 9) * D + n0]);
        v.z = bf16x2(w1[k0 * D + n1],       w1[(k0 + 1) * D + n1]);
        v.w = bf16x2(w1[(k0 + 8) * D + n1], w1[(k0 + 9) * D + n1]);
        btab[idx] = v;
    }
    if (tid < D) { w1b[tid] = w1[D * D + tid]; w2s[tid] = w2[tid]; }

    // ---- prefetch macro: nb 96x32 f4 (16/thr), it 8x32 f4, nbw 24 f4 ----
    #define PREFETCH(TILE, PB) do {                                               \
        const int _rb = (TILE) * MTILE;                                           \
        const int _ib = (TILE) * ITEMS_PER_TILE;                                  \
        float* _nbd = nbbuf + (PB) * NBSZ;                                        \
        _Pragma("unroll")                                                         \
        for (int _i = 0; _i < 16; _i++) {                                         \
            const int _idx = tid + _i * NTHREADS;                                 \
            const int _r = _idx >> 5, _l4 = _idx & 31;                            \
            cp16(smem_u32(&_nbd[_r * D + _l4 * 4]),                               \
                 (const float4*)nbh + (size_t)(_rb + _r) * 32 + _l4);             \
        }                                                                         \
        float* _itd = itbuf + (PB) * ITSZ;                                        \
        _Pragma("unroll")                                                         \
        for (int _i = 0; _i < 2; _i++) {                                          \
            const int _idx = tid + _i * NTHREADS;                                 \
            if (_idx < ITEMS_PER_TILE * 32)                                       \
                cp16(smem_u32(&_itd[_idx * 4]),                                   \
                     (const float4*)item + (size_t)_ib * 32 + _idx);              \
        }                                                                         \
        if (tid < MTILE / 4)                                                      \
            cp16(smem_u32(&nbwbuf[(PB) * MTILE + tid * 4]),                       \
                 (const float4*)nbw + (size_t)(TILE) * (MTILE / 4) + tid);        \
    } while (0)

    // ---- pipeline prologue ----
    int pb = 0;
    if (blockIdx.x < ntiles) PREFETCH(blockIdx.x, 0);
    cp_commit();
    __syncthreads();   // btab/w1b/w2s visible

    for (int tile = blockIdx.x; tile < ntiles; tile += gridDim.x) {
        const int itembase = tile * ITEMS_PER_TILE;
        const int nxt = tile + gridDim.x;
        if (nxt < ntiles) PREFETCH(nxt, pb ^ 1);
        cp_commit();
        cp_wait1();
        __syncthreads();

        const float* nb   = nbbuf + pb * NBSZ;
        const float* it   = itbuf + pb * ITSZ;
        const float* nbws = nbwbuf + pb * MTILE;

        // ---- build bf16 feat from resident fp32 SMEM ----
        #pragma unroll
        for (int i = 0; i < (MTILE * 32) / NTHREADS; i++) {   // 16 iters
            const int idx = tid + i * NTHREADS;
            const int r = idx >> 5, l4 = idx & 31;
            float4 a = *(const float4*)&nb[r * D + l4 * 4];
            float4 b = *(const float4*)&it[((unsigned)r / 12u) * D + l4 * 4];
            uint2 pk;
            pk.x = bf16x2(a.x * b.x, a.y * b.y);
            pk.y = bf16x2(a.z * b.z, a.w * b.w);
            *(uint2*)&feat[r * FLDF + l4 * 4] = pk;
        }
        __syncthreads();

        // ---- mainloop: one m16 tile per warp, N=128, bf16 k16 ----
        float acc[16][4];
        #pragma unroll
        for (int j = 0; j < 16; j++)
            #pragma unroll
            for (int q = 0; q < 4; q++) acc[j][q] = 0.f;

        #pragma unroll 1
        for (int ks = 0; ks < KSTEPS; ks++) {
            const int k0 = ks * 16 + 2 * c;
            uint32_t a0 = *(const uint32_t*)&feat[(wrow + g) * FLDF + k0];
            uint32_t a1 = *(const uint32_t*)&feat[(wrow + g + 8) * FLDF + k0];
            uint32_t a2 = *(const uint32_t*)&feat[(wrow + g) * FLDF + k0 + 8];
            uint32_t a3 = *(const uint32_t*)&feat[(wrow + g + 8) * FLDF + k0 + 8];
            const uint4* bks = &btab[ks * 8 * 32];
            #pragma unroll
            for (int p = 0; p < 8; p++) {
                uint4 b = bks[p * 32 + lane];
                mma_bf16(acc[2 * p],     a0, a1, a2, a3, b.x, b.y);
                mma_bf16(acc[2 * p + 1], a0, a1, a2, a3, b.z, b.w);
            }
        }

        // ---- logits: bias, lrelu, dot w2, reduce over c ----
        {
            const int r0 = wrow + g, r1 = r0 + 8;
            const float nbw0 = nbws[r0];
            const float nbw1 = nbws[r1];
            float l0 = 0.f, l1 = 0.f;
            #pragma unroll
            for (int j = 0; j < 16; j++) {
                float2 wb = *(const float2*)&w1b[j * 8 + 2 * c];
                float2 wv = *(const float2*)&w2s[j * 8 + 2 * c];
                l0 = fmaf(lrelu(fmaf(nbw0, wb.x, acc[j][0])), wv.x, l0);
                l0 = fmaf(lrelu(fmaf(nbw0, wb.y, acc[j][1])), wv.y, l0);
                l1 = fmaf(lrelu(fmaf(nbw1, wb.x, acc[j][2])), wv.x, l1);
                l1 = fmaf(lrelu(fmaf(nbw1, wb.y, acc[j][3])), wv.y, l1);
            }
            l0 += __shfl_xor_sync(0xffffffffu, l0, 1);
            l0 += __shfl_xor_sync(0xffffffffu, l0, 2);
            l1 += __shfl_xor_sync(0xffffffffu, l1, 1);
            l1 += __shfl_xor_sync(0xffffffffu, l1, 2);
            if (c == 0) { lgs[r0] = l0; lgs[r1] = l1; }
        }
        __syncthreads();

        // ---- softmax per item ----
        if (tid < ITEMS_PER_TILE) {
            const int base = tid * S;
            float m = lgs[base];
            #pragma unroll
            for (int s = 1; s < S; s++) m = fmaxf(m, lgs[base + s]);
            float e[S]; float sum = 0.f;
            #pragma unroll
            for (int s = 0; s < S; s++) { e[s] = __expf(lgs[base + s] - m); sum += e[s]; }
            const float inv = 1.f / sum;
            #pragma unroll
            for (int s = 0; s < S; s++) alps[base + s] = e[s] * inv;
        }
        __syncthreads();

        // ---- weighted neighbor sum from resident fp32 SMEM ----
        for (int idx = tid; idx < ITEMS_PER_TILE * 32; idx += NTHREADS) {
            const int i = idx >> 5, l4 = idx & 31;
            const float* al  = &alps[i * S];
            const float* nbp = &nb[(i * S) * D + l4 * 4];
            float4 o = make_float4(0.f, 0.f, 0.f, 0.f);
            #pragma unroll
            for (int s = 0; s < S; s++) {
                float4 v = *(const float4*)&nbp[s * D];
                const float a = al[s];
                o.x = fmaf(a, v.x, o.x); o.y = fmaf(a, v.y, o.y);
                o.z = fmaf(a, v.z, o.z); o.w = fmaf(a, v.w, o.w);
            }
            *(float4*)&out[(size_t)(itembase + i) * D + l4 * 4] = o;
        }
        __syncthreads();   // protect buffers before next prefetch
        pb ^= 1;
    }
}

// ---- final gating: 1 item per block (measured-best), FFMA2 dual GEMV ----
#define FMA2(acc, a, b) \
    asm("fma.rn.f32x2 %0, %1, %2, %0;" : "+l"(acc) : "l"(a), "l"(b))
__device__ __forceinline__ unsigned long long pack_f32(float lo, float hi) {
    unsigned long long p;
    asm("mov.b64 %0, {%1, %2};" : "=l"(p) : "r"(__float_as_uint(lo)), "r"(__float_as_uint(hi)));
    return p;
}
__device__ __forceinline__ void unpack_f32(unsigned long long p, float& lo, float& hi) {
    asm("mov.b64 {%0, %1}, %2;" : "=f"(lo), "=f"(hi) : "l"(p));
}

__global__ __launch_bounds__(128) void final_kernel(
    const float* __restrict__ hidden, const float* __restrict__ agg_a,
    const float* __restrict__ agg_c,  const float* __restrict__ w3,
    const float* __restrict__ w4,     const float* __restrict__ sv,
    float* __restrict__ out)
{
    const int n = blockIdx.x;
    const int t = threadIdx.x;
    __shared__ unsigned long long sh_hg[D];

    const float s0 = sv[0], s1 = sv[1];
    float h = hidden[(size_t)n * D + t];
    float g = s0 * agg_a[(size_t)n * D + t] + s1 * agg_c[(size_t)n * D + t];
    sh_hg[t] = pack_f32(h, g);
    __syncthreads();

    unsigned long long acc = 0;
    const float* w3c = w3 + t;
    const float* w4c = w4 + t;
    #pragma unroll 4
    for (int k = 0; k < D; k++) {
        unsigned long long wp = pack_f32(__ldg(&w3c[k * D]), __ldg(&w4c[k * D]));
        FMA2(acc, sh_hg[k], wp);
    }
    float a0, a1;
    unpack_f32(acc, a0, a1);
    float wgt = 1.f / (1.f + __expf(-(a0 + a1)));
    out[(size_t)n * D + t] = (1.f - wgt) * h + wgt * g;
}

extern "C" void kernel_launch(void* const* d_in, const int* in_sizes, int n_in,
                              void* d_out, int out_size)
{
    const float* hidden = (const float*)d_in[0];
    const float* nh1    = (const float*)d_in[1];
    const float* nh2    = (const float*)d_in[2];
    const float* nw0    = (const float*)d_in[3];
    const float* nw1    = (const float*)d_in[4];
    const float* w1     = (const float*)d_in[5];
    const float* w2     = (const float*)d_in[6];
    const float* w3     = (const float*)d_in[7];
    const float* w4     = (const float*)d_in[8];
    const float* sv     = (const float*)d_in[9];
    float* out = (float*)d_out;

    float *agg_a, *agg_b, *agg_c;
    cudaGetSymbolAddress((void**)&agg_a, g_agg_a);
    cudaGetSymbolAddress((void**)&agg_b, g_agg_b);
    cudaGetSymbolAddress((void**)&agg_c, g_agg_c);

    cudaFuncSetAttribute(fused_agg_kernel,
                         cudaFuncAttributeMaxDynamicSharedMemorySize, SMEM_BYTES);

    const int GP = 148;
    const int T0 = 3200  / ITEMS_PER_TILE;   // 400 tiles (exact)
    const int T1 = 38400 / ITEMS_PER_TILE;   // 4800 tiles (exact)

    // hop 1
    fused_agg_kernel<<<GP, NTHREADS, SMEM_BYTES>>>(hidden, nh1, nw0, w1, w2, agg_a, T0);
    fused_agg_kernel<<<GP, NTHREADS, SMEM_BYTES>>>(nh1,    nh2, nw1, w1, w2, agg_b, T1);
    // hop 2
    fused_agg_kernel<<<GP, NTHREADS, SMEM_BYTES>>>(agg_a,  agg_b, nw0, w1, w2, agg_c, T0);
    // gate
    final_kernel<<<3200, 128>>>(hidden, agg_a, agg_c, w3, w4, sv, out);
}

// round 11
// speedup vs baseline: 2.1379x; 1.1759x over previous
#include <cuda_runtime.h>
#include <cstdint>

#define D 128
#define S 12
#define ITEMS_PER_TILE 8
#define MTILE 96             // 6 row-tiles x 16 rows; 12 warps = (rowtile, N-half)
#define NTHREADS 384
#define KSTEPS 8             // K=128, 16 per bf16 mma
#define FLDF 136             // bf16 feat row stride (elems)

// ---- scratch (allocation-free rule) ----
__device__ float g_agg_a[3200  * 128];
__device__ float g_agg_b[38400 * 128];
__device__ float g_agg_c[3200  * 128];

#define NBSZ   (MTILE * D)              // 12288 floats per nb buffer
#define ITSZ   (ITEMS_PER_TILE * D)     // 1024
#define FEAT_BYTES (MTILE * FLDF * 2)   // 26112
#define BTAB_BYTES (KSTEPS * 8 * 32 * 16) // 32768
#define SMEM_BYTES (2 * NBSZ * 4 + 2 * ITSZ * 4 + FEAT_BYTES + BTAB_BYTES \
                    + 256 * 4 + 2 * MTILE * 4 + 2 * MTILE * 4 + MTILE * 4)

__device__ __forceinline__ uint32_t bf16x2(float lo, float hi) {
    uint32_t r;
    asm("cvt.rn.bf16x2.f32 %0, %1, %2;" : "=r"(r) : "f"(hi), "f"(lo));
    return r;
}
__device__ __forceinline__ void mma_bf16(float* d, uint32_t a0, uint32_t a1,
                                         uint32_t a2, uint32_t a3,
                                         uint32_t b0, uint32_t b1) {
    asm volatile(
        "mma.sync.aligned.m16n8k16.row.col.f32.bf16.bf16.f32 "
        "{%0,%1,%2,%3}, {%4,%5,%6,%7}, {%8,%9}, {%0,%1,%2,%3};"
        : "+f"(d[0]), "+f"(d[1]), "+f"(d[2]), "+f"(d[3])
        : "r"(a0), "r"(a1), "r"(a2), "r"(a3), "r"(b0), "r"(b1));
}
__device__ __forceinline__ float lrelu(float x) { return x > 0.f ? x : 0.2f * x; }

__device__ __forceinline__ void cp16(uint32_t smem_dst, const void* gsrc) {
    asm volatile("cp.async.cg.shared.global [%0], [%1], 16;" :: "r"(smem_dst), "l"(gsrc));
}
__device__ __forceinline__ void cp_commit() {
    asm volatile("cp.async.commit_group;");
}
__device__ __forceinline__ void cp_wait1() {
    asm volatile("cp.async.wait_group 1;" ::: "memory");
}
__device__ __forceinline__ uint32_t smem_u32(const void* p) {
    return (uint32_t)__cvta_generic_to_shared(p);
}

// Fused aggregate: cp.async double-buffered; 12 warps = 6 rowtiles x 2 N-halves.
__global__ __launch_bounds__(NTHREADS, 1) void fused_agg_kernel(
    const float* __restrict__ item, const float* __restrict__ nbh,
    const float* __restrict__ nbw,  const float* __restrict__ w1,
    const float* __restrict__ w2,   float* __restrict__ out,
    int ntiles)
{
    extern __shared__ char smraw[];
    float*    nbbuf  = (float*)smraw;                         // [2][96*128]
    float*    itbuf  = nbbuf + 2 * NBSZ;                      // [2][8*128]
    uint16_t* feat   = (uint16_t*)(itbuf + 2 * ITSZ);         // [96][136] bf16
    uint4*    btab   = (uint4*)((char*)feat + FEAT_BYTES);    // [8][8][32]
    float*    w1b    = (float*)((char*)btab + BTAB_BYTES);    // [128]
    float*    w2s    = w1b + 128;                             // [128]
    float*    nbwbuf = w2s + 128;                             // [2][96]
    float*    lgs2   = nbwbuf + 2 * MTILE;                    // [2][96]
    float*    alps   = lgs2 + 2 * MTILE;                      // [96]

    const int tid  = threadIdx.x;
    const int lane = tid & 31;
    const int warp = tid >> 5;
    const int c  = lane & 3;
    const int g  = lane >> 2;
    const int rt = warp >> 1;       // row-tile 0..5
    const int nh = warp & 1;        // N-half 0..1
    const int wrow = rt * 16;

    // ---- one-time: btab uint4 (two adjacent n-tiles per entry), bias row, w2 ----
    for (int idx = tid; idx < KSTEPS * 8 * 32; idx += NTHREADS) {
        const int t  = idx & 31;
        const int p  = (idx >> 5) & 7;
        const int ks = idx >> 8;
        const int tc = t & 3, tg = t >> 2;
        const int k0 = ks * 16 + 2 * tc;
        const int n0 = (2 * p) * 8 + tg;
        const int n1 = (2 * p + 1) * 8 + tg;
        uint4 v;
        v.x = bf16x2(w1[k0 * D + n0],       w1[(k0 + 1) * D + n0]);
        v.y = bf16x2(w1[(k0 + 8) * D + n0], w1[(k0 + 9) * D + n0]);
        v.z = bf16x2(w1[k0 * D + n1],       w1[(k0 + 1) * D + n1]);
        v.w = bf16x2(w1[(k0 + 8) * D + n1], w1[(k0 + 9) * D + n1]);
        btab[idx] = v;
    }
    if (tid < D) { w1b[tid] = w1[D * D + tid]; w2s[tid] = w2[tid]; }

    #define PREFETCH(TILE, PB) do {                                               \
        const int _rb = (TILE) * MTILE;                                           \
        const int _ib = (TILE) * ITEMS_PER_TILE;                                  \
        float* _nbd = nbbuf + (PB) * NBSZ;                                        \
        _Pragma("unroll")                                                         \
        for (int _i = 0; _i < 8; _i++) {                                          \
            const int _idx = tid + _i * NTHREADS;                                 \
            const int _r = _idx >> 5, _l4 = _idx & 31;                            \
            cp16(smem_u32(&_nbd[_r * D + _l4 * 4]),                               \
                 (const float4*)nbh + (size_t)(_rb + _r) * 32 + _l4);             \
        }                                                                         \
        float* _itd = itbuf + (PB) * ITSZ;                                        \
        if (tid < ITEMS_PER_TILE * 32)                                            \
            cp16(smem_u32(&_itd[tid * 4]),                                        \
                 (const float4*)item + (size_t)_ib * 32 + tid);                   \
        if (tid < MTILE / 4)                                                      \
            cp16(smem_u32(&nbwbuf[(PB) * MTILE + tid * 4]),                       \
                 (const float4*)nbw + (size_t)(TILE) * (MTILE / 4) + tid);        \
    } while (0)

    int pb = 0;
    if (blockIdx.x < ntiles) PREFETCH(blockIdx.x, 0);
    cp_commit();
    __syncthreads();

    for (int tile = blockIdx.x; tile < ntiles; tile += gridDim.x) {
        const int itembase = tile * ITEMS_PER_TILE;
        const int nxt = tile + gridDim.x;
        if (nxt < ntiles) PREFETCH(nxt, pb ^ 1);
        cp_commit();
        cp_wait1();
        __syncthreads();

        const float* nb   = nbbuf + pb * NBSZ;
        const float* it   = itbuf + pb * ITSZ;
        const float* nbws = nbwbuf + pb * MTILE;

        // ---- build bf16 feat from resident fp32 SMEM (8 iters) ----
        #pragma unroll
        for (int i = 0; i < (MTILE * 32) / NTHREADS; i++) {
            const int idx = tid + i * NTHREADS;
            const int r = idx >> 5, l4 = idx & 31;
            float4 a = *(const float4*)&nb[r * D + l4 * 4];
            float4 b = *(const float4*)&it[((unsigned)r / 12u) * D + l4 * 4];
            uint2 pk;
            pk.x = bf16x2(a.x * b.x, a.y * b.y);
            pk.y = bf16x2(a.z * b.z, a.w * b.w);
            *(uint2*)&feat[r * FLDF + l4 * 4] = pk;
        }
        __syncthreads();

        // ---- mainloop: m16 rows [wrow,wrow+16), cols [nh*64, nh*64+64) ----
        float acc[8][4];
        #pragma unroll
        for (int j = 0; j < 8; j++)
            #pragma unroll
            for (int q = 0; q < 4; q++) acc[j][q] = 0.f;

        #pragma unroll 1
        for (int ks = 0; ks < KSTEPS; ks++) {
            const int k0 = ks * 16 + 2 * c;
            uint32_t a0 = *(const uint32_t*)&feat[(wrow + g) * FLDF + k0];
            uint32_t a1 = *(const uint32_t*)&feat[(wrow + g + 8) * FLDF + k0];
            uint32_t a2 = *(const uint32_t*)&feat[(wrow + g) * FLDF + k0 + 8];
            uint32_t a3 = *(const uint32_t*)&feat[(wrow + g + 8) * FLDF + k0 + 8];
            const uint4* bks = &btab[ks * 8 * 32 + nh * 4 * 32];
            #pragma unroll
            for (int pp = 0; pp < 4; pp++) {
                uint4 b = bks[pp * 32 + lane];
                mma_bf16(acc[2 * pp],     a0, a1, a2, a3, b.x, b.y);
                mma_bf16(acc[2 * pp + 1], a0, a1, a2, a3, b.z, b.w);
            }
        }

        // ---- partial logits for this N-half ----
        {
            const int r0 = wrow + g, r1 = r0 + 8;
            const float nbw0 = nbws[r0];
            const float nbw1 = nbws[r1];
            float l0 = 0.f, l1 = 0.f;
            #pragma unroll
            for (int j = 0; j < 8; j++) {
                const int jj = nh * 8 + j;
                float2 wb = *(const float2*)&w1b[jj * 8 + 2 * c];
                float2 wv = *(const float2*)&w2s[jj * 8 + 2 * c];
                l0 = fmaf(lrelu(fmaf(nbw0, wb.x, acc[j][0])), wv.x, l0);
                l0 = fmaf(lrelu(fmaf(nbw0, wb.y, acc[j][1])), wv.y, l0);
                l1 = fmaf(lrelu(fmaf(nbw1, wb.x, acc[j][2])), wv.x, l1);
                l1 = fmaf(lrelu(fmaf(nbw1, wb.y, acc[j][3])), wv.y, l1);
            }
            l0 += __shfl_xor_sync(0xffffffffu, l0, 1);
            l0 += __shfl_xor_sync(0xffffffffu, l0, 2);
            l1 += __shfl_xor_sync(0xffffffffu, l1, 1);
            l1 += __shfl_xor_sync(0xffffffffu, l1, 2);
            if (c == 0) { lgs2[nh * MTILE + r0] = l0; lgs2[nh * MTILE + r1] = l1; }
        }
        __syncthreads();

        // ---- softmax per item (combine N-half partials) ----
        if (tid < ITEMS_PER_TILE) {
            const int base = tid * S;
            float lg[S];
            #pragma unroll
            for (int s = 0; s < S; s++)
                lg[s] = lgs2[base + s] + lgs2[MTILE + base + s];
            float m = lg[0];
            #pragma unroll
            for (int s = 1; s < S; s++) m = fmaxf(m, lg[s]);
            float e[S]; float sum = 0.f;
            #pragma unroll
            for (int s = 0; s < S; s++) { e[s] = __expf(lg[s] - m); sum += e[s]; }
            const float inv = 1.f / sum;
            #pragma unroll
            for (int s = 0; s < S; s++) alps[base + s] = e[s] * inv;
        }
        __syncthreads();

        // ---- weighted neighbor sum from resident fp32 SMEM ----
        if (tid < ITEMS_PER_TILE * 32) {
            const int i = tid >> 5, l4 = tid & 31;
            const float* al  = &alps[i * S];
            const float* nbp = &nb[(i * S) * D + l4 * 4];
            float4 o = make_float4(0.f, 0.f, 0.f, 0.f);
            #pragma unroll
            for (int s = 0; s < S; s++) {
                float4 v = *(const float4*)&nbp[s * D];
                const float a = al[s];
                o.x = fmaf(a, v.x, o.x); o.y = fmaf(a, v.y, o.y);
                o.z = fmaf(a, v.z, o.z); o.w = fmaf(a, v.w, o.w);
            }
            *(float4*)&out[(size_t)(itembase + i) * D + tid * 4 - i * 128] = o;
        }
        __syncthreads();
        pb ^= 1;
    }
}

// ---- final gating: persistent, SMEM-staged fp32 (w3,w4) table ----
#define FB_ITEMS 16
#define FIN_SMEM ((128 * 128 + FB_ITEMS * 128) * 8)

#define FMA2(acc, a, b) \
    asm("fma.rn.f32x2 %0, %1, %2, %0;" : "+l"(acc) : "l"(a), "l"(b))
__device__ __forceinline__ void unpack_f32(unsigned long long p, float& lo, float& hi) {
    asm("mov.b64 {%0, %1}, %2;" : "=f"(lo), "=f"(hi) : "l"(p));
}

__global__ __launch_bounds__(256, 1) void final_kernel(
    const float* __restrict__ hidden, const float* __restrict__ agg_a,
    const float* __restrict__ agg_c,  const float* __restrict__ w3,
    const float* __restrict__ w4,     const float* __restrict__ sv,
    float* __restrict__ out, int nchunks)
{
    extern __shared__ float2 fsm[];
    float2* wq = fsm;                    // [128*128] (w3,w4) interleaved
    float2* hg = wq + 128 * 128;         // [16][128] (h,g)

    const int tid  = threadIdx.x;
    const int lane = tid & 31;
    const int warp = tid >> 5;
    const float s0 = sv[0], s1 = sv[1];

    // one-time: stage weights (coalesced)
    for (int idx = tid; idx < 128 * 128; idx += 256)
        wq[idx] = make_float2(w3[idx], w4[idx]);

    for (int chunk = blockIdx.x; chunk < nchunks; chunk += gridDim.x) {
        const int ibase = chunk * FB_ITEMS;
        // stage hg for 16 items
        for (int idx = tid; idx < FB_ITEMS * 128; idx += 256) {
            const size_t off = (size_t)ibase * 128 + idx;
            hg[idx] = make_float2(hidden[off], s0 * agg_a[off] + s1 * agg_c[off]);
        }
        __syncthreads();

        // warp handles 2 items; lane owns cols lane+32j
        const int i0 = warp * 2;
        unsigned long long acc[2][4] = {{0,0,0,0},{0,0,0,0}};
        const float2* hg0 = &hg[i0 * 128];
        const float2* hg1 = &hg[(i0 + 1) * 128];
        #pragma unroll 4
        for (int k = 0; k < 128; k++) {
            const float2* wrow = &wq[k * 128 + lane];
            unsigned long long h0 = *(const unsigned long long*)&hg0[k];
            unsigned long long h1 = *(const unsigned long long*)&hg1[k];
            #pragma unroll
            for (int j = 0; j < 4; j++) {
                unsigned long long wv = *(const unsigned long long*)&wrow[32 * j];
                FMA2(acc[0][j], h0, wv);
                FMA2(acc[1][j], h1, wv);
            }
        }
        #pragma unroll
        for (int q = 0; q < 2; q++) {
            const int n = ibase + i0 + q;
            #pragma unroll
            for (int j = 0; j < 4; j++) {
                const int col = lane + 32 * j;
                float a0, a1;
                unpack_f32(acc[q][j], a0, a1);
                const float wgt = 1.f / (1.f + __expf(-(a0 + a1)));
                float2 v = hg[(i0 + q) * 128 + col];
                out[(size_t)n * 128 + col] = (1.f - wgt) * v.x + wgt * v.y;
            }
        }
        __syncthreads();
    }
}

extern "C" void kernel_launch(void* const* d_in, const int* in_sizes, int n_in,
                              void* d_out, int out_size)
{
    const float* hidden = (const float*)d_in[0];
    const float* nh1    = (const float*)d_in[1];
    const float* nh2    = (const float*)d_in[2];
    const float* nw0    = (const float*)d_in[3];
    const float* nw1    = (const float*)d_in[4];
    const float* w1     = (const float*)d_in[5];
    const float* w2     = (const float*)d_in[6];
    const float* w3     = (const float*)d_in[7];
    const float* w4     = (const float*)d_in[8];
    const float* sv     = (const float*)d_in[9];
    float* out = (float*)d_out;

    float *agg_a, *agg_b, *agg_c;
    cudaGetSymbolAddress((void**)&agg_a, g_agg_a);
    cudaGetSymbolAddress((void**)&agg_b, g_agg_b);
    cudaGetSymbolAddress((void**)&agg_c, g_agg_c);

    cudaFuncSetAttribute(fused_agg_kernel,
                         cudaFuncAttributeMaxDynamicSharedMemorySize, SMEM_BYTES);
    cudaFuncSetAttribute(final_kernel,
                         cudaFuncAttributeMaxDynamicSharedMemorySize, FIN_SMEM);

    const int GP = 148;
    const int T0 = 3200  / ITEMS_PER_TILE;   // 400 tiles
    const int T1 = 38400 / ITEMS_PER_TILE;   // 4800 tiles

    // hop 1
    fused_agg_kernel<<<GP, NTHREADS, SMEM_BYTES>>>(hidden, nh1, nw0, w1, w2, agg_a, T0);
    fused_agg_kernel<<<GP, NTHREADS, SMEM_BYTES>>>(nh1,    nh2, nw1, w1, w2, agg_b, T1);
    // hop 2
    fused_agg_kernel<<<GP, NTHREADS, SMEM_BYTES>>>(agg_a,  agg_b, nw0, w1, w2, agg_c, T0);
    // gate
    final_kernel<<<GP, 256, FIN_SMEM>>>(hidden, agg_a, agg_c, w3, w4, sv, out,
                                        3200 / FB_ITEMS);
}

// round 12
// speedup vs baseline: 2.1960x; 1.0272x over previous
#include <cuda_runtime.h>
#include <cstdint>

#define D 128
#define S 12
#define ITEMS_PER_TILE 8
#define MTILE 96             // 6 row-tiles x 16 rows; 12 warps = (rowtile, N-half)
#define NTHREADS 384
#define KSTEPS 8             // K=128, 16 per bf16 mma
#define FLDF 136             // bf16 feat row stride (elems)

// ---- scratch (allocation-free rule) ----
__device__ float g_agg_a[3200  * 128];
__device__ float g_agg_b[38400 * 128];
__device__ float g_agg_c[3200  * 128];

#define NBSZ   (MTILE * D)
#define ITSZ   (ITEMS_PER_TILE * D)
#define FEAT_BYTES (MTILE * FLDF * 2)
#define BTAB_BYTES (KSTEPS * 8 * 32 * 16)
#define SMEM_BYTES (2 * NBSZ * 4 + 2 * ITSZ * 4 + FEAT_BYTES + BTAB_BYTES \
                    + 256 * 4 + 2 * MTILE * 4 + 2 * MTILE * 4)

__device__ __forceinline__ uint32_t bf16x2(float lo, float hi) {
    uint32_t r;
    asm("cvt.rn.bf16x2.f32 %0, %1, %2;" : "=r"(r) : "f"(hi), "f"(lo));
    return r;
}
__device__ __forceinline__ void mma_bf16(float* d, uint32_t a0, uint32_t a1,
                                         uint32_t a2, uint32_t a3,
                                         uint32_t b0, uint32_t b1) {
    asm volatile(
        "mma.sync.aligned.m16n8k16.row.col.f32.bf16.bf16.f32 "
        "{%0,%1,%2,%3}, {%4,%5,%6,%7}, {%8,%9}, {%0,%1,%2,%3};"
        : "+f"(d[0]), "+f"(d[1]), "+f"(d[2]), "+f"(d[3])
        : "r"(a0), "r"(a1), "r"(a2), "r"(a3), "r"(b0), "r"(b1));
}
__device__ __forceinline__ float lrelu(float x) { return x > 0.f ? x : 0.2f * x; }

__device__ __forceinline__ void cp16(uint32_t smem_dst, const void* gsrc) {
    asm volatile("cp.async.cg.shared.global [%0], [%1], 16;" :: "r"(smem_dst), "l"(gsrc));
}
__device__ __forceinline__ void cp_commit() {
    asm volatile("cp.async.commit_group;");
}
__device__ __forceinline__ void cp_wait1() {
    asm volatile("cp.async.wait_group 1;" ::: "memory");
}
__device__ __forceinline__ uint32_t smem_u32(const void* p) {
    return (uint32_t)__cvta_generic_to_shared(p);
}

// Fused aggregate handling TWO workloads in one launch (tile < ntA -> A else B).
__global__ __launch_bounds__(NTHREADS, 1) void fused_agg_kernel(
    const float* __restrict__ itemA, const float* __restrict__ nbhA,
    const float* __restrict__ nbwA,  float* __restrict__ outA, int ntA,
    const float* __restrict__ itemB, const float* __restrict__ nbhB,
    const float* __restrict__ nbwB,  float* __restrict__ outB, int ntB,
    const float* __restrict__ w1,    const float* __restrict__ w2)
{
    extern __shared__ char smraw[];
    float*    nbbuf  = (float*)smraw;                         // [2][96*128]
    float*    itbuf  = nbbuf + 2 * NBSZ;                      // [2][8*128]
    uint16_t* feat   = (uint16_t*)(itbuf + 2 * ITSZ);         // [96][136] bf16
    uint4*    btab   = (uint4*)((char*)feat + FEAT_BYTES);    // [8][8][32]
    float*    w1b    = (float*)((char*)btab + BTAB_BYTES);    // [128]
    float*    w2s    = w1b + 128;                             // [128]
    float*    nbwbuf = w2s + 128;                             // [2][96]
    float*    lgs2   = nbwbuf + 2 * MTILE;                    // [2][96]

    const int tid  = threadIdx.x;
    const int lane = tid & 31;
    const int warp = tid >> 5;
    const int c  = lane & 3;
    const int g  = lane >> 2;
    const int rt = warp >> 1;
    const int nh = warp & 1;
    const int wrow = rt * 16;
    const int ntiles = ntA + ntB;

    // ---- one-time: btab, bias row, w2 ----
    for (int idx = tid; idx < KSTEPS * 8 * 32; idx += NTHREADS) {
        const int t  = idx & 31;
        const int p  = (idx >> 5) & 7;
        const int ks = idx >> 8;
        const int tc = t & 3, tg = t >> 2;
        const int k0 = ks * 16 + 2 * tc;
        const int n0 = (2 * p) * 8 + tg;
        const int n1 = (2 * p + 1) * 8 + tg;
        uint4 v;
        v.x = bf16x2(w1[k0 * D + n0],       w1[(k0 + 1) * D + n0]);
        v.y = bf16x2(w1[(k0 + 8) * D + n0], w1[(k0 + 9) * D + n0]);
        v.z = bf16x2(w1[k0 * D + n1],       w1[(k0 + 1) * D + n1]);
        v.w = bf16x2(w1[(k0 + 8) * D + n1], w1[(k0 + 9) * D + n1]);
        btab[idx] = v;
    }
    if (tid < D) { w1b[tid] = w1[D * D + tid]; w2s[tid] = w2[tid]; }

    // resolve workload + prefetch tile T into buffer PB
    #define PREFETCH(T, PB) do {                                                  \
        const int _isA = (T) < ntA;                                               \
        const int _lt  = _isA ? (T) : (T) - ntA;                                  \
        const float* _it = _isA ? itemA : itemB;                                  \
        const float* _nb = _isA ? nbhA  : nbhB;                                   \
        const float* _nw = _isA ? nbwA  : nbwB;                                   \
        const int _rb = _lt * MTILE;                                              \
        const int _ib = _lt * ITEMS_PER_TILE;                                     \
        float* _nbd = nbbuf + (PB) * NBSZ;                                        \
        _Pragma("unroll")                                                         \
        for (int _i = 0; _i < 8; _i++) {                                          \
            const int _idx = tid + _i * NTHREADS;                                 \
            const int _r = _idx >> 5, _l4 = _idx & 31;                            \
            cp16(smem_u32(&_nbd[_r * D + _l4 * 4]),                               \
                 (const float4*)_nb + (size_t)(_rb + _r) * 32 + _l4);             \
        }                                                                         \
        float* _itd = itbuf + (PB) * ITSZ;                                        \
        if (tid < ITEMS_PER_TILE * 32)                                            \
            cp16(smem_u32(&_itd[tid * 4]),                                        \
                 (const float4*)_it + (size_t)_ib * 32 + tid);                    \
        if (tid < MTILE / 4)                                                      \
            cp16(smem_u32(&nbwbuf[(PB) * MTILE + tid * 4]),                       \
                 (const float4*)_nw + (size_t)_lt * (MTILE / 4) + tid);           \
    } while (0)

    int pb = 0;
    if (blockIdx.x < ntiles) PREFETCH(blockIdx.x, 0);
    cp_commit();
    __syncthreads();

    for (int tile = blockIdx.x; tile < ntiles; tile += gridDim.x) {
        const int isA = tile < ntA;
        const int lt  = isA ? tile : tile - ntA;
        float* outp   = isA ? outA : outB;
        const int itembase = lt * ITEMS_PER_TILE;

        const int nxt = tile + gridDim.x;
        if (nxt < ntiles) PREFETCH(nxt, pb ^ 1);
        cp_commit();
        cp_wait1();
        __syncthreads();

        const float* nb   = nbbuf + pb * NBSZ;
        const float* it   = itbuf + pb * ITSZ;
        const float* nbws = nbwbuf + pb * MTILE;

        // ---- build bf16 feat ----
        #pragma unroll
        for (int i = 0; i < (MTILE * 32) / NTHREADS; i++) {
            const int idx = tid + i * NTHREADS;
            const int r = idx >> 5, l4 = idx & 31;
            float4 a = *(const float4*)&nb[r * D + l4 * 4];
            float4 b = *(const float4*)&it[((unsigned)r / 12u) * D + l4 * 4];
            uint2 pk;
            pk.x = bf16x2(a.x * b.x, a.y * b.y);
            pk.y = bf16x2(a.z * b.z, a.w * b.w);
            *(uint2*)&feat[r * FLDF + l4 * 4] = pk;
        }
        __syncthreads();

        // ---- mainloop ----
        float acc[8][4];
        #pragma unroll
        for (int j = 0; j < 8; j++)
            #pragma unroll
            for (int q = 0; q < 4; q++) acc[j][q] = 0.f;

        #pragma unroll 1
        for (int ks = 0; ks < KSTEPS; ks++) {
            const int k0 = ks * 16 + 2 * c;
            uint32_t a0 = *(const uint32_t*)&feat[(wrow + g) * FLDF + k0];
            uint32_t a1 = *(const uint32_t*)&feat[(wrow + g + 8) * FLDF + k0];
            uint32_t a2 = *(const uint32_t*)&feat[(wrow + g) * FLDF + k0 + 8];
            uint32_t a3 = *(const uint32_t*)&feat[(wrow + g + 8) * FLDF + k0 + 8];
            const uint4* bks = &btab[ks * 8 * 32 + nh * 4 * 32];
            #pragma unroll
            for (int pp = 0; pp < 4; pp++) {
                uint4 b = bks[pp * 32 + lane];
                mma_bf16(acc[2 * pp],     a0, a1, a2, a3, b.x, b.y);
                mma_bf16(acc[2 * pp + 1], a0, a1, a2, a3, b.z, b.w);
            }
        }

        // ---- partial logits for this N-half ----
        {
            const int r0 = wrow + g, r1 = r0 + 8;
            const float nbw0 = nbws[r0];
            const float nbw1 = nbws[r1];
            float l0 = 0.f, l1 = 0.f;
            #pragma unroll
            for (int j = 0; j < 8; j++) {
                const int jj = nh * 8 + j;
                float2 wb = *(const float2*)&w1b[jj * 8 + 2 * c];
                float2 wv = *(const float2*)&w2s[jj * 8 + 2 * c];
                l0 = fmaf(lrelu(fmaf(nbw0, wb.x, acc[j][0])), wv.x, l0);
                l0 = fmaf(lrelu(fmaf(nbw0, wb.y, acc[j][1])), wv.y, l0);
                l1 = fmaf(lrelu(fmaf(nbw1, wb.x, acc[j][2])), wv.x, l1);
                l1 = fmaf(lrelu(fmaf(nbw1, wb.y, acc[j][3])), wv.y, l1);
            }
            l0 += __shfl_xor_sync(0xffffffffu, l0, 1);
            l0 += __shfl_xor_sync(0xffffffffu, l0, 2);
            l1 += __shfl_xor_sync(0xffffffffu, l1, 1);
            l1 += __shfl_xor_sync(0xffffffffu, l1, 2);
            if (c == 0) { lgs2[nh * MTILE + r0] = l0; lgs2[nh * MTILE + r1] = l1; }
        }
        __syncthreads();

        // ---- epilogue: inline softmax (per-warp redundant) + weighted sum ----
        if (tid < ITEMS_PER_TILE * 32) {
            const int i = tid >> 5, l4 = tid & 31;
            const int base = i * S;
            float lg[S];
            #pragma unroll
            for (int s = 0; s < S; s++)
                lg[s] = lgs2[base + s] + lgs2[MTILE + base + s];   // broadcast
            float m = lg[0];
            #pragma unroll
            for (int s = 1; s < S; s++) m = fmaxf(m, lg[s]);
            float e[S]; float sum = 0.f;
            #pragma unroll
            for (int s = 0; s < S; s++) { e[s] = __expf(lg[s] - m); sum += e[s]; }
            const float inv = 1.f / sum;

            const float* nbp = &nb[(i * S) * D + l4 * 4];
            float4 o = make_float4(0.f, 0.f, 0.f, 0.f);
            #pragma unroll
            for (int s = 0; s < S; s++) {
                float4 v = *(const float4*)&nbp[s * D];
                const float a = e[s] * inv;
                o.x = fmaf(a, v.x, o.x); o.y = fmaf(a, v.y, o.y);
                o.z = fmaf(a, v.z, o.z); o.w = fmaf(a, v.w, o.w);
            }
            *(float4*)&outp[(size_t)(itembase + i) * D + l4 * 4] = o;
        }
        __syncthreads();
        pb ^= 1;
    }
}

// ---- final gating: 8 warps x 4 items, SMEM-staged (w3,w4); grid 100 ----
#define FB_ITEMS 32
#define FIN_SMEM ((128 * 128 + FB_ITEMS * 128) * 8)

#define FMA2(acc, a, b) \
    asm("fma.rn.f32x2 %0, %1, %2, %0;" : "+l"(acc) : "l"(a), "l"(b))
__device__ __forceinline__ void unpack_f32(unsigned long long p, float& lo, float& hi) {
    asm("mov.b64 {%0, %1}, %2;" : "=f"(lo), "=f"(hi) : "l"(p));
}

__global__ __launch_bounds__(256, 1) void final_kernel(
    const float* __restrict__ hidden, const float* __restrict__ agg_a,
    const float* __restrict__ agg_c,  const float* __restrict__ w3,
    const float* __restrict__ w4,     const float* __restrict__ sv,
    float* __restrict__ out)
{
    extern __shared__ float2 fsm[];
    float2* wq = fsm;                    // [128*128] (w3,w4) interleaved
    float2* hg = wq + 128 * 128;         // [32][128] (h,g)

    const int tid  = threadIdx.x;
    const int lane = tid & 31;
    const int warp = tid >> 5;
    const float s0 = sv[0], s1 = sv[1];

    for (int idx = tid; idx < 128 * 128; idx += 256)
        wq[idx] = make_float2(w3[idx], w4[idx]);

    const int ibase = blockIdx.x * FB_ITEMS;
    for (int idx = tid; idx < FB_ITEMS * 128; idx += 256) {
        const size_t off = (size_t)ibase * 128 + idx;
        hg[idx] = make_float2(hidden[off], s0 * agg_a[off] + s1 * agg_c[off]);
    }
    __syncthreads();

    // warp handles 4 items; lane owns cols lane+32j
    const int i0 = warp * 4;
    unsigned long long acc[4][4];
    #pragma unroll
    for (int q = 0; q < 4; q++)
        #pragma unroll
        for (int j = 0; j < 4; j++) acc[q][j] = 0ULL;

    #pragma unroll 2
    for (int k = 0; k < 128; k++) {
        const float2* wrow = &wq[k * 128 + lane];
        unsigned long long wv0 = *(const unsigned long long*)&wrow[0];
        unsigned long long wv1 = *(const unsigned long long*)&wrow[32];
        unsigned long long wv2 = *(const unsigned long long*)&wrow[64];
        unsigned long long wv3 = *(const unsigned long long*)&wrow[96];
        #pragma unroll
        for (int q = 0; q < 4; q++) {
            unsigned long long hq = *(const unsigned long long*)&hg[(i0 + q) * 128 + k];
            FMA2(acc[q][0], hq, wv0);
            FMA2(acc[q][1], hq, wv1);
            FMA2(acc[q][2], hq, wv2);
            FMA2(acc[q][3], hq, wv3);
        }
    }
    #pragma unroll
    for (int q = 0; q < 4; q++) {
        const int n = ibase + i0 + q;
        #pragma unroll
        for (int j = 0; j < 4; j++) {
            const int col = lane + 32 * j;
            float a0, a1;
            unpack_f32(acc[q][j], a0, a1);
            const float wgt = 1.f / (1.f + __expf(-(a0 + a1)));
            float2 v = hg[(i0 + q) * 128 + col];
            out[(size_t)n * 128 + col] = (1.f - wgt) * v.x + wgt * v.y;
        }
    }
}

extern "C" void kernel_launch(void* const* d_in, const int* in_sizes, int n_in,
                              void* d_out, int out_size)
{
    const float* hidden = (const float*)d_in[0];
    const float* nh1    = (const float*)d_in[1];
    const float* nh2    = (const float*)d_in[2];
    const float* nw0    = (const float*)d_in[3];
    const float* nw1    = (const float*)d_in[4];
    const float* w1     = (const float*)d_in[5];
    const float* w2     = (const float*)d_in[6];
    const float* w3     = (const float*)d_in[7];
    const float* w4     = (const float*)d_in[8];
    const float* sv     = (const float*)d_in[9];
    float* out = (float*)d_out;

    float *agg_a, *agg_b, *agg_c;
    cudaGetSymbolAddress((void**)&agg_a, g_agg_a);
    cudaGetSymbolAddress((void**)&agg_b, g_agg_b);
    cudaGetSymbolAddress((void**)&agg_c, g_agg_c);

    cudaFuncSetAttribute(fused_agg_kernel,
                         cudaFuncAttributeMaxDynamicSharedMemorySize, SMEM_BYTES);
    cudaFuncSetAttribute(final_kernel,
                         cudaFuncAttributeMaxDynamicSharedMemorySize, FIN_SMEM);

    const int GP = 148;
    const int T0 = 3200  / ITEMS_PER_TILE;   // 400 tiles
    const int T1 = 38400 / ITEMS_PER_TILE;   // 4800 tiles

    // hop 1: both levels merged into one launch (A = big, B = small)
    fused_agg_kernel<<<GP, NTHREADS, SMEM_BYTES>>>(
        nh1, nh2, nw1, agg_b, T1,
        hidden, nh1, nw0, agg_a, T0,
        w1, w2);
    // hop 2 (single workload: B side empty)
    fused_agg_kernel<<<GP, NTHREADS, SMEM_BYTES>>>(
        agg_a, agg_b, nw0, agg_c, T0,
        agg_a, agg_b, nw0, agg_c, 0,
        w1, w2);
    // gate
    final_kernel<<<100, 256, FIN_SMEM>>>(hidden, agg_a, agg_c, w3, w4, sv, out);
}

// round 13
// speedup vs baseline: 2.2714x; 1.0343x over previous
#include <cuda_runtime.h>
#include <cstdint>

#define D 128
#define S 12
#define ITEMS_PER_TILE 8
#define MTILE 96             // 3 rowgroups x 32 rows; 12 warps = (rowgroup, N-quarter)
#define NTHREADS 384
#define KSTEPS 8             // K=128, 16 per bf16 mma
#define FLDF 136             // bf16 feat row stride (elems)

// ---- scratch (allocation-free rule) ----
__device__ float g_agg_a[3200  * 128];
__device__ float g_agg_b[38400 * 128];
__device__ float g_agg_c[3200  * 128];

#define NBSZ   (MTILE * D)
#define ITSZ   (ITEMS_PER_TILE * D)
#define FEAT_BYTES (MTILE * FLDF * 2)
#define BTAB_BYTES (KSTEPS * 8 * 32 * 16)
#define SMEM_BYTES (2 * NBSZ * 4 + 2 * ITSZ * 4 + FEAT_BYTES + BTAB_BYTES \
                    + 256 * 4 + 2 * MTILE * 4 + 4 * MTILE * 4)

__device__ __forceinline__ uint32_t bf16x2(float lo, float hi) {
    uint32_t r;
    asm("cvt.rn.bf16x2.f32 %0, %1, %2;" : "=r"(r) : "f"(hi), "f"(lo));
    return r;
}
__device__ __forceinline__ void mma_bf16(float* d, uint32_t a0, uint32_t a1,
                                         uint32_t a2, uint32_t a3,
                                         uint32_t b0, uint32_t b1) {
    asm volatile(
        "mma.sync.aligned.m16n8k16.row.col.f32.bf16.bf16.f32 "
        "{%0,%1,%2,%3}, {%4,%5,%6,%7}, {%8,%9}, {%0,%1,%2,%3};"
        : "+f"(d[0]), "+f"(d[1]), "+f"(d[2]), "+f"(d[3])
        : "r"(a0), "r"(a1), "r"(a2), "r"(a3), "r"(b0), "r"(b1));
}
__device__ __forceinline__ float lrelu(float x) { return x > 0.f ? x : 0.2f * x; }

__device__ __forceinline__ void cp16(uint32_t smem_dst, const void* gsrc) {
    asm volatile("cp.async.cg.shared.global [%0], [%1], 16;" :: "r"(smem_dst), "l"(gsrc));
}
__device__ __forceinline__ void cp_commit() {
    asm volatile("cp.async.commit_group;");
}
__device__ __forceinline__ void cp_wait1() {
    asm volatile("cp.async.wait_group 1;" ::: "memory");
}
__device__ __forceinline__ uint32_t smem_u32(const void* p) {
    return (uint32_t)__cvta_generic_to_shared(p);
}

// Fused aggregate, two workloads per launch; B fragments register-resident.
__global__ __launch_bounds__(NTHREADS, 1) void fused_agg_kernel(
    const float* __restrict__ itemA, const float* __restrict__ nbhA,
    const float* __restrict__ nbwA,  float* __restrict__ outA, int ntA,
    const float* __restrict__ itemB, const float* __restrict__ nbhB,
    const float* __restrict__ nbwB,  float* __restrict__ outB, int ntB,
    const float* __restrict__ w1,    const float* __restrict__ w2)
{
    extern __shared__ char smraw[];
    float*    nbbuf  = (float*)smraw;                         // [2][96*128]
    float*    itbuf  = nbbuf + 2 * NBSZ;                      // [2][8*128]
    uint16_t* feat   = (uint16_t*)(itbuf + 2 * ITSZ);         // [96][136] bf16
    uint4*    btab   = (uint4*)((char*)feat + FEAT_BYTES);    // [8][8][32]
    float*    w1b    = (float*)((char*)btab + BTAB_BYTES);    // [128]
    float*    w2s    = w1b + 128;                             // [128]
    float*    nbwbuf = w2s + 128;                             // [2][96]
    float*    lgs4   = nbwbuf + 2 * MTILE;                    // [4][96]

    const int tid  = threadIdx.x;
    const int lane = tid & 31;
    const int warp = tid >> 5;
    const int c  = lane & 3;
    const int g  = lane >> 2;
    const int rt = warp >> 2;       // rowgroup 0..2 (32 rows)
    const int nq = warp & 3;        // N-quarter 0..3 (32 cols)
    const int m0 = rt * 32 + g;
    const int ntiles = ntA + ntB;

    // ---- one-time: btab staged to SMEM, then each warp grabs its quarter ----
    for (int idx = tid; idx < KSTEPS * 8 * 32; idx += NTHREADS) {
        const int t  = idx & 31;
        const int p  = (idx >> 5) & 7;
        const int ks = idx >> 8;
        const int tc = t & 3, tg = t >> 2;
        const int k0 = ks * 16 + 2 * tc;
        const int n0 = (2 * p) * 8 + tg;
        const int n1 = (2 * p + 1) * 8 + tg;
        uint4 v;
        v.x = bf16x2(w1[k0 * D + n0],       w1[(k0 + 1) * D + n0]);
        v.y = bf16x2(w1[(k0 + 8) * D + n0], w1[(k0 + 9) * D + n0]);
        v.z = bf16x2(w1[k0 * D + n1],       w1[(k0 + 1) * D + n1]);
        v.w = bf16x2(w1[(k0 + 8) * D + n1], w1[(k0 + 9) * D + n1]);
        btab[idx] = v;
    }
    if (tid < D) { w1b[tid] = w1[D * D + tid]; w2s[tid] = w2[tid]; }
    __syncthreads();

    // B fragments for this warp's N-quarter, register-resident for whole kernel
    uint4 breg[KSTEPS][2];
    #pragma unroll
    for (int ks = 0; ks < KSTEPS; ks++) {
        breg[ks][0] = btab[ks * 256 + (2 * nq) * 32 + lane];
        breg[ks][1] = btab[ks * 256 + (2 * nq + 1) * 32 + lane];
    }

    #define PREFETCH(T, PB) do {                                                  \
        const int _isA = (T) < ntA;                                               \
        const int _lt  = _isA ? (T) : (T) - ntA;                                  \
        const float* _it = _isA ? itemA : itemB;                                  \
        const float* _nb = _isA ? nbhA  : nbhB;                                   \
        const float* _nw = _isA ? nbwA  : nbwB;                                   \
        const int _rb = _lt * MTILE;                                              \
        const int _ib = _lt * ITEMS_PER_TILE;                                     \
        float* _nbd = nbbuf + (PB) * NBSZ;                                        \
        _Pragma("unroll")                                                         \
        for (int _i = 0; _i < 8; _i++) {                                          \
            const int _idx = tid + _i * NTHREADS;                                 \
            const int _r = _idx >> 5, _l4 = _idx & 31;                            \
            cp16(smem_u32(&_nbd[_r * D + _l4 * 4]),                               \
                 (const float4*)_nb + (size_t)(_rb + _r) * 32 + _l4);             \
        }                                                                         \
        float* _itd = itbuf + (PB) * ITSZ;                                        \
        if (tid < ITEMS_PER_TILE * 32)                                            \
            cp16(smem_u32(&_itd[tid * 4]),                                        \
                 (const float4*)_it + (size_t)_ib * 32 + tid);                    \
        if (tid < MTILE / 4)                                                      \
            cp16(smem_u32(&nbwbuf[(PB) * MTILE + tid * 4]),                       \
                 (const float4*)_nw + (size_t)_lt * (MTILE / 4) + tid);           \
    } while (0)

    int pb = 0;
    if (blockIdx.x < ntiles) PREFETCH(blockIdx.x, 0);
    cp_commit();

    for (int tile = blockIdx.x; tile < ntiles; tile += gridDim.x) {
        const int isA = tile < ntA;
        const int lt  = isA ? tile : tile - ntA;
        float* outp   = isA ? outA : outB;
        const int itembase = lt * ITEMS_PER_TILE;

        const int nxt = tile + gridDim.x;
        if (nxt < ntiles) PREFETCH(nxt, pb ^ 1);
        cp_commit();
        cp_wait1();
        __syncthreads();

        const float* nb   = nbbuf + pb * NBSZ;
        const float* it   = itbuf + pb * ITSZ;
        const float* nbws = nbwbuf + pb * MTILE;

        // ---- build bf16 feat ----
        #pragma unroll
        for (int i = 0; i < (MTILE * 32) / NTHREADS; i++) {
            const int idx = tid + i * NTHREADS;
            const int r = idx >> 5, l4 = idx & 31;
            float4 a = *(const float4*)&nb[r * D + l4 * 4];
            float4 b = *(const float4*)&it[((unsigned)r / 12u) * D + l4 * 4];
            uint2 pk;
            pk.x = bf16x2(a.x * b.x, a.y * b.y);
            pk.y = bf16x2(a.z * b.z, a.w * b.w);
            *(uint2*)&feat[r * FLDF + l4 * 4] = pk;
        }
        __syncthreads();

        // ---- mainloop: rows [rt*32, rt*32+32), cols [nq*32, nq*32+32) ----
        // acc[half][nt][4]: half = m16 tile (rows +0/+16), nt = n-tile in quarter
        float acc[2][4][4];
        #pragma unroll
        for (int h = 0; h < 2; h++)
            #pragma unroll
            for (int j = 0; j < 4; j++)
                #pragma unroll
                for (int q = 0; q < 4; q++) acc[h][j][q] = 0.f;

        #pragma unroll
        for (int ks = 0; ks < KSTEPS; ks++) {
            const int k0 = ks * 16 + 2 * c;
            const uint16_t* f0 = &feat[m0 * FLDF + k0];
            uint32_t a00 = *(const uint32_t*)(f0);
            uint32_t a01 = *(const uint32_t*)(f0 + 8 * FLDF);
            uint32_t a02 = *(const uint32_t*)(f0 + 8);
            uint32_t a03 = *(const uint32_t*)(f0 + 8 * FLDF + 8);
            uint32_t a10 = *(const uint32_t*)(f0 + 16 * FLDF);
            uint32_t a11 = *(const uint32_t*)(f0 + 24 * FLDF);
            uint32_t a12 = *(const uint32_t*)(f0 + 16 * FLDF + 8);
            uint32_t a13 = *(const uint32_t*)(f0 + 24 * FLDF + 8);
            const uint4 b0 = breg[ks][0], b1 = breg[ks][1];
            mma_bf16(acc[0][0], a00, a01, a02, a03, b0.x, b0.y);
            mma_bf16(acc[0][1], a00, a01, a02, a03, b0.z, b0.w);
            mma_bf16(acc[0][2], a00, a01, a02, a03, b1.x, b1.y);
            mma_bf16(acc[0][3], a00, a01, a02, a03, b1.z, b1.w);
            mma_bf16(acc[1][0], a10, a11, a12, a13, b0.x, b0.y);
            mma_bf16(acc[1][1], a10, a11, a12, a13, b0.z, b0.w);
            mma_bf16(acc[1][2], a10, a11, a12, a13, b1.x, b1.y);
            mma_bf16(acc[1][3], a10, a11, a12, a13, b1.z, b1.w);
        }

        // ---- partial logits for this N-quarter (2 m16 halves) ----
        #pragma unroll
        for (int h = 0; h < 2; h++) {
            const int r0 = rt * 32 + h * 16 + g, r1 = r0 + 8;
            const float nbw0 = nbws[r0];
            const float nbw1 = nbws[r1];
            float l0 = 0.f, l1 = 0.f;
            #pragma unroll
            for (int j = 0; j < 4; j++) {
                const int jj = nq * 4 + j;
                float2 wb = *(const float2*)&w1b[jj * 8 + 2 * c];
                float2 wv = *(const float2*)&w2s[jj * 8 + 2 * c];
                l0 = fmaf(lrelu(fmaf(nbw0, wb.x, acc[h][j][0])), wv.x, l0);
                l0 = fmaf(lrelu(fmaf(nbw0, wb.y, acc[h][j][1])), wv.y, l0);
                l1 = fmaf(lrelu(fmaf(nbw1, wb.x, acc[h][j][2])), wv.x, l1);
                l1 = fmaf(lrelu(fmaf(nbw1, wb.y, acc[h][j][3])), wv.y, l1);
            }
            l0 += __shfl_xor_sync(0xffffffffu, l0, 1);
            l0 += __shfl_xor_sync(0xffffffffu, l0, 2);
            l1 += __shfl_xor_sync(0xffffffffu, l1, 1);
            l1 += __shfl_xor_sync(0xffffffffu, l1, 2);
            if (c == 0) { lgs4[nq * MTILE + r0] = l0; lgs4[nq * MTILE + r1] = l1; }
        }
        __syncthreads();

        // ---- epilogue: inline softmax (combine 4 quarters) + weighted sum ----
        if (tid < ITEMS_PER_TILE * 32) {
            const int i = tid >> 5, l4 = tid & 31;
            const int base = i * S;
            float lg[S];
            #pragma unroll
            for (int s = 0; s < S; s++)
                lg[s] = (lgs4[base + s] + lgs4[MTILE + base + s])
                      + (lgs4[2 * MTILE + base + s] + lgs4[3 * MTILE + base + s]);
            float m = lg[0];
            #pragma unroll
            for (int s = 1; s < S; s++) m = fmaxf(m, lg[s]);
            float e[S]; float sum = 0.f;
            #pragma unroll
            for (int s = 0; s < S; s++) { e[s] = __expf(lg[s] - m); sum += e[s]; }
            const float inv = 1.f / sum;

            const float* nbp = &nb[(i * S) * D + l4 * 4];
            float4 o = make_float4(0.f, 0.f, 0.f, 0.f);
            #pragma unroll
            for (int s = 0; s < S; s++) {
                float4 v = *(const float4*)&nbp[s * D];
                const float a = e[s] * inv;
                o.x = fmaf(a, v.x, o.x); o.y = fmaf(a, v.y, o.y);
                o.z = fmaf(a, v.z, o.z); o.w = fmaf(a, v.w, o.w);
            }
            *(float4*)&outp[(size_t)(itembase + i) * D + l4 * 4] = o;
        }
        __syncthreads();
        pb ^= 1;
    }
}

// ---- final gating: 8 warps x 4 items, SMEM-staged (w3,w4); grid 100 ----
#define FB_ITEMS 32
#define FIN_SMEM ((128 * 128 + FB_ITEMS * 128) * 8)

#define FMA2(acc, a, b) \
    asm("fma.rn.f32x2 %0, %1, %2, %0;" : "+l"(acc) : "l"(a), "l"(b))
__device__ __forceinline__ void unpack_f32(unsigned long long p, float& lo, float& hi) {
    asm("mov.b64 {%0, %1}, %2;" : "=f"(lo), "=f"(hi) : "l"(p));
}

__global__ __launch_bounds__(256, 1) void final_kernel(
    const float* __restrict__ hidden, const float* __restrict__ agg_a,
    const float* __restrict__ agg_c,  const float* __restrict__ w3,
    const float* __restrict__ w4,     const float* __restrict__ sv,
    float* __restrict__ out)
{
    extern __shared__ float2 fsm[];
    float2* wq = fsm;                    // [128*128] (w3,w4) interleaved
    float2* hg = wq + 128 * 128;         // [32][128] (h,g)

    const int tid  = threadIdx.x;
    const int lane = tid & 31;
    const int warp = tid >> 5;
    const float s0 = sv[0], s1 = sv[1];

    for (int idx = tid; idx < 128 * 128; idx += 256)
        wq[idx] = make_float2(w3[idx], w4[idx]);

    const int ibase = blockIdx.x * FB_ITEMS;
    for (int idx = tid; idx < FB_ITEMS * 128; idx += 256) {
        const size_t off = (size_t)ibase * 128 + idx;
        hg[idx] = make_float2(hidden[off], s0 * agg_a[off] + s1 * agg_c[off]);
    }
    __syncthreads();

    const int i0 = warp * 4;
    unsigned long long acc[4][4];
    #pragma unroll
    for (int q = 0; q < 4; q++)
        #pragma unroll
        for (int j = 0; j < 4; j++) acc[q][j] = 0ULL;

    #pragma unroll 2
    for (int k = 0; k < 128; k++) {
        const float2* wrow = &wq[k * 128 + lane];
        unsigned long long wv0 = *(const unsigned long long*)&wrow[0];
        unsigned long long wv1 = *(const unsigned long long*)&wrow[32];
        unsigned long long wv2 = *(const unsigned long long*)&wrow[64];
        unsigned long long wv3 = *(const unsigned long long*)&wrow[96];
        #pragma unroll
        for (int q = 0; q < 4; q++) {
            unsigned long long hq = *(const unsigned long long*)&hg[(i0 + q) * 128 + k];
            FMA2(acc[q][0], hq, wv0);
            FMA2(acc[q][1], hq, wv1);
            FMA2(acc[q][2], hq, wv2);
            FMA2(acc[q][3], hq, wv3);
        }
    }
    #pragma unroll
    for (int q = 0; q < 4; q++) {
        const int n = ibase + i0 + q;
        #pragma unroll
        for (int j = 0; j < 4; j++) {
            const int col = lane + 32 * j;
            float a0, a1;
            unpack_f32(acc[q][j], a0, a1);
            const float wgt = 1.f / (1.f + __expf(-(a0 + a1)));
            float2 v = hg[(i0 + q) * 128 + col];
            out[(size_t)n * 128 + col] = (1.f - wgt) * v.x + wgt * v.y;
        }
    }
}

extern "C" void kernel_launch(void* const* d_in, const int* in_sizes, int n_in,
                              void* d_out, int out_size)
{
    const float* hidden = (const float*)d_in[0];
    const float* nh1    = (const float*)d_in[1];
    const float* nh2    = (const float*)d_in[2];
    const float* nw0    = (const float*)d_in[3];
    const float* nw1    = (const float*)d_in[4];
    const float* w1     = (const float*)d_in[5];
    const float* w2     = (const float*)d_in[6];
    const float* w3     = (const float*)d_in[7];
    const float* w4     = (const float*)d_in[8];
    const float* sv     = (const float*)d_in[9];
    float* out = (float*)d_out;

    float *agg_a, *agg_b, *agg_c;
    cudaGetSymbolAddress((void**)&agg_a, g_agg_a);
    cudaGetSymbolAddress((void**)&agg_b, g_agg_b);
    cudaGetSymbolAddress((void**)&agg_c, g_agg_c);

    cudaFuncSetAttribute(fused_agg_kernel,
                         cudaFuncAttributeMaxDynamicSharedMemorySize, SMEM_BYTES);
    cudaFuncSetAttribute(final_kernel,
                         cudaFuncAttributeMaxDynamicSharedMemorySize, FIN_SMEM);

    const int GP = 148;
    const int T0 = 3200  / ITEMS_PER_TILE;   // 400 tiles
    const int T1 = 38400 / ITEMS_PER_TILE;   // 4800 tiles

    // hop 1: both levels merged (A = big, B = small)
    fused_agg_kernel<<<GP, NTHREADS, SMEM_BYTES>>>(
        nh1, nh2, nw1, agg_b, T1,
        hidden, nh1, nw0, agg_a, T0,
        w1, w2);
    // hop 2
    fused_agg_kernel<<<GP, NTHREADS, SMEM_BYTES>>>(
        agg_a, agg_b, nw0, agg_c, T0,
        agg_a, agg_b, nw0, agg_c, 0,
        w1, w2);
    // gate
    final_kernel<<<100, 256, FIN_SMEM>>>(hidden, agg_a, agg_c, w3, w4, sv, out);
}

// round 14
// speedup vs baseline: 2.2936x; 1.0098x over previous
#include <cuda_runtime.h>
#include <cstdint>

#define D 128
#define S 12
#define ITEMS_PER_TILE 4
#define MTILE 48             // 3 rowtiles x 16 rows; 6 warps = (rowtile, N-half)
#define NTHREADS 192
#define KSTEPS 8             // K=128, 16 per bf16 mma
#define FLDF 136             // bf16 feat row stride (elems)

// ---- scratch (allocation-free rule) ----
__device__ float g_agg_a[3200  * 128];
__device__ float g_agg_b[38400 * 128];
__device__ float g_agg_c[3200  * 128];

#define NBSZ   (MTILE * D)              // 6144 floats
#define ITSZ   (ITEMS_PER_TILE * D)     // 512
#define FEAT_BYTES (MTILE * FLDF * 2)   // 13056
#define BTAB_BYTES (KSTEPS * 8 * 32 * 16) // 32768
#define SMEM_BYTES (2 * NBSZ * 4 + 2 * ITSZ * 4 + FEAT_BYTES + BTAB_BYTES \
                    + 256 * 4 + 2 * MTILE * 4 + 2 * MTILE * 4)   // ~98.5 KB

__device__ __forceinline__ uint32_t bf16x2(float lo, float hi) {
    uint32_t r;
    asm("cvt.rn.bf16x2.f32 %0, %1, %2;" : "=r"(r) : "f"(hi), "f"(lo));
    return r;
}
__device__ __forceinline__ void mma_bf16(float* d, uint32_t a0, uint32_t a1,
                                         uint32_t a2, uint32_t a3,
                                         uint32_t b0, uint32_t b1) {
    asm volatile(
        "mma.sync.aligned.m16n8k16.row.col.f32.bf16.bf16.f32 "
        "{%0,%1,%2,%3}, {%4,%5,%6,%7}, {%8,%9}, {%0,%1,%2,%3};"
        : "+f"(d[0]), "+f"(d[1]), "+f"(d[2]), "+f"(d[3])
        : "r"(a0), "r"(a1), "r"(a2), "r"(a3), "r"(b0), "r"(b1));
}
__device__ __forceinline__ float lrelu(float x) { return x > 0.f ? x : 0.2f * x; }

__device__ __forceinline__ void cp16(uint32_t smem_dst, const void* gsrc) {
    asm volatile("cp.async.cg.shared.global [%0], [%1], 16;" :: "r"(smem_dst), "l"(gsrc));
}
__device__ __forceinline__ void cp_commit() {
    asm volatile("cp.async.commit_group;");
}
__device__ __forceinline__ void cp_wait1() {
    asm volatile("cp.async.wait_group 1;" ::: "memory");
}
__device__ __forceinline__ uint32_t smem_u32(const void* p) {
    return (uint32_t)__cvta_generic_to_shared(p);
}

// Fused aggregate, two workloads per launch; 2 CTAs co-resident per SM.
__global__ __launch_bounds__(NTHREADS, 2) void fused_agg_kernel(
    const float* __restrict__ itemA, const float* __restrict__ nbhA,
    const float* __restrict__ nbwA,  float* __restrict__ outA, int ntA,
    const float* __restrict__ itemB, const float* __restrict__ nbhB,
    const float* __restrict__ nbwB,  float* __restrict__ outB, int ntB,
    const float* __restrict__ w1,    const float* __restrict__ w2)
{
    extern __shared__ char smraw[];
    float*    nbbuf  = (float*)smraw;                         // [2][48*128]
    float*    itbuf  = nbbuf + 2 * NBSZ;                      // [2][4*128]
    uint16_t* feat   = (uint16_t*)(itbuf + 2 * ITSZ);         // [48][136] bf16
    uint4*    btab   = (uint4*)((char*)feat + FEAT_BYTES);    // [8][8][32]
    float*    w1b    = (float*)((char*)btab + BTAB_BYTES);    // [128]
    float*    w2s    = w1b + 128;                             // [128]
    float*    nbwbuf = w2s + 128;                             // [2][48]
    float*    lgs2   = nbwbuf + 2 * MTILE;                    // [2][48]

    const int tid  = threadIdx.x;
    const int lane = tid & 31;
    const int warp = tid >> 5;
    const int c  = lane & 3;
    const int g  = lane >> 2;
    const int rt = warp >> 1;       // rowtile 0..2 (16 rows)
    const int nh = warp & 1;        // N-half 0..1 (64 cols)
    const int m0 = rt * 16 + g;
    const int ntiles = ntA + ntB;

    // ---- one-time: btab, bias row, w2 ----
    for (int idx = tid; idx < KSTEPS * 8 * 32; idx += NTHREADS) {
        const int t  = idx & 31;
        const int p  = (idx >> 5) & 7;
        const int ks = idx >> 8;
        const int tc = t & 3, tg = t >> 2;
        const int k0 = ks * 16 + 2 * tc;
        const int n0 = (2 * p) * 8 + tg;
        const int n1 = (2 * p + 1) * 8 + tg;
        uint4 v;
        v.x = bf16x2(w1[k0 * D + n0],       w1[(k0 + 1) * D + n0]);
        v.y = bf16x2(w1[(k0 + 8) * D + n0], w1[(k0 + 9) * D + n0]);
        v.z = bf16x2(w1[k0 * D + n1],       w1[(k0 + 1) * D + n1]);
        v.w = bf16x2(w1[(k0 + 8) * D + n1], w1[(k0 + 9) * D + n1]);
        btab[idx] = v;
    }
    if (tid < D) { w1b[tid] = w1[D * D + tid]; w2s[tid] = w2[tid]; }

    #define PREFETCH(T, PB) do {                                                  \
        const int _isA = (T) < ntA;                                               \
        const int _lt  = _isA ? (T) : (T) - ntA;                                  \
        const float* _it = _isA ? itemA : itemB;                                  \
        const float* _nb = _isA ? nbhA  : nbhB;                                   \
        const float* _nw = _isA ? nbwA  : nbwB;                                   \
        const int _rb = _lt * MTILE;                                              \
        const int _ib = _lt * ITEMS_PER_TILE;                                     \
        float* _nbd = nbbuf + (PB) * NBSZ;                                        \
        _Pragma("unroll")                                                         \
        for (int _i = 0; _i < 8; _i++) {                                          \
            const int _idx = tid + _i * NTHREADS;                                 \
            const int _r = _idx >> 5, _l4 = _idx & 31;                            \
            cp16(smem_u32(&_nbd[_r * D + _l4 * 4]),                               \
                 (const float4*)_nb + (size_t)(_rb + _r) * 32 + _l4);             \
        }                                                                         \
        float* _itd = itbuf + (PB) * ITSZ;                                        \
        if (tid < ITEMS_PER_TILE * 32)                                            \
            cp16(smem_u32(&_itd[tid * 4]),                                        \
                 (const float4*)_it + (size_t)_ib * 32 + tid);                    \
        if (tid < MTILE / 4)                                                      \
            cp16(smem_u32(&nbwbuf[(PB) * MTILE + tid * 4]),                       \
                 (const float4*)_nw + (size_t)_lt * (MTILE / 4) + tid);           \
    } while (0)

    int pb = 0;
    if (blockIdx.x < ntiles) PREFETCH(blockIdx.x, 0);
    cp_commit();
    __syncthreads();

    for (int tile = blockIdx.x; tile < ntiles; tile += gridDim.x) {
        const int isA = tile < ntA;
        const int lt  = isA ? tile : tile - ntA;
        float* outp   = isA ? outA : outB;
        const int itembase = lt * ITEMS_PER_TILE;

        const int nxt = tile + gridDim.x;
        if (nxt < ntiles) PREFETCH(nxt, pb ^ 1);
        cp_commit();
        cp_wait1();
        __syncthreads();

        const float* nb   = nbbuf + pb * NBSZ;
        const float* it   = itbuf + pb * ITSZ;
        const float* nbws = nbwbuf + pb * MTILE;

        // ---- build bf16 feat (48x32 f4 / 192 thr = 8 iters) ----
        #pragma unroll
        for (int i = 0; i < (MTILE * 32) / NTHREADS; i++) {
            const int idx = tid + i * NTHREADS;
            const int r = idx >> 5, l4 = idx & 31;
            float4 a = *(const float4*)&nb[r * D + l4 * 4];
            float4 b = *(const float4*)&it[((unsigned)r / 12u) * D + l4 * 4];
            uint2 pk;
            pk.x = bf16x2(a.x * b.x, a.y * b.y);
            pk.y = bf16x2(a.z * b.z, a.w * b.w);
            *(uint2*)&feat[r * FLDF + l4 * 4] = pk;
        }
        __syncthreads();

        // ---- mainloop: rows [rt*16, rt*16+16), cols [nh*64, nh*64+64) ----
        float acc[8][4];
        #pragma unroll
        for (int j = 0; j < 8; j++)
            #pragma unroll
            for (int q = 0; q < 4; q++) acc[j][q] = 0.f;

        #pragma unroll
        for (int ks = 0; ks < KSTEPS; ks++) {
            const int k0 = ks * 16 + 2 * c;
            const uint16_t* f0 = &feat[m0 * FLDF + k0];
            uint32_t a0 = *(const uint32_t*)(f0);
            uint32_t a1 = *(const uint32_t*)(f0 + 8 * FLDF);
            uint32_t a2 = *(const uint32_t*)(f0 + 8);
            uint32_t a3 = *(const uint32_t*)(f0 + 8 * FLDF + 8);
            const uint4* bks = &btab[ks * 256 + nh * 4 * 32];
            #pragma unroll
            for (int pp = 0; pp < 4; pp++) {
                uint4 b = bks[pp * 32 + lane];
                mma_bf16(acc[2 * pp],     a0, a1, a2, a3, b.x, b.y);
                mma_bf16(acc[2 * pp + 1], a0, a1, a2, a3, b.z, b.w);
            }
        }

        // ---- partial logits for this N-half ----
        {
            const int r0 = m0, r1 = m0 + 8;
            const float nbw0 = nbws[r0];
            const float nbw1 = nbws[r1];
            float l0 = 0.f, l1 = 0.f;
            #pragma unroll
            for (int j = 0; j < 8; j++) {
                const int jj = nh * 8 + j;
                float2 wb = *(const float2*)&w1b[jj * 8 + 2 * c];
                float2 wv = *(const float2*)&w2s[jj * 8 + 2 * c];
                l0 = fmaf(lrelu(fmaf(nbw0, wb.x, acc[j][0])), wv.x, l0);
                l0 = fmaf(lrelu(fmaf(nbw0, wb.y, acc[j][1])), wv.y, l0);
                l1 = fmaf(lrelu(fmaf(nbw1, wb.x, acc[j][2])), wv.x, l1);
                l1 = fmaf(lrelu(fmaf(nbw1, wb.y, acc[j][3])), wv.y, l1);
            }
            l0 += __shfl_xor_sync(0xffffffffu, l0, 1);
            l0 += __shfl_xor_sync(0xffffffffu, l0, 2);
            l1 += __shfl_xor_sync(0xffffffffu, l1, 1);
            l1 += __shfl_xor_sync(0xffffffffu, l1, 2);
            if (c == 0) { lgs2[nh * MTILE + r0] = l0; lgs2[nh * MTILE + r1] = l1; }
        }
        __syncthreads();

        // ---- epilogue: inline softmax (combine halves) + weighted sum ----
        if (tid < ITEMS_PER_TILE * 32) {
            const int i = tid >> 5, l4 = tid & 31;
            const int base = i * S;
            float lg[S];
            #pragma unroll
            for (int s = 0; s < S; s++)
                lg[s] = lgs2[base + s] + lgs2[MTILE + base + s];
            float m = lg[0];
            #pragma unroll
            for (int s = 1; s < S; s++) m = fmaxf(m, lg[s]);
            float e[S]; float sum = 0.f;
            #pragma unroll
            for (int s = 0; s < S; s++) { e[s] = __expf(lg[s] - m); sum += e[s]; }
            const float inv = 1.f / sum;

            const float* nbp = &nb[(i * S) * D + l4 * 4];
            float4 o = make_float4(0.f, 0.f, 0.f, 0.f);
            #pragma unroll
            for (int s = 0; s < S; s++) {
                float4 v = *(const float4*)&nbp[s * D];
                const float a = e[s] * inv;
                o.x = fmaf(a, v.x, o.x); o.y = fmaf(a, v.y, o.y);
                o.z = fmaf(a, v.z, o.z); o.w = fmaf(a, v.w, o.w);
            }
            *(float4*)&outp[(size_t)(itembase + i) * D + l4 * 4] = o;
        }
        __syncthreads();
        pb ^= 1;
    }
}

// ---- final gating: 8 warps x 4 items, SMEM-staged (w3,w4); grid 100 ----
#define FB_ITEMS 32
#define FIN_SMEM ((128 * 128 + FB_ITEMS * 128) * 8)

#define FMA2(acc, a, b) \
    asm("fma.rn.f32x2 %0, %1, %2, %0;" : "+l"(acc) : "l"(a), "l"(b))
__device__ __forceinline__ void unpack_f32(unsigned long long p, float& lo, float& hi) {
    asm("mov.b64 {%0, %1}, %2;" : "=f"(lo), "=f"(hi) : "l"(p));
}

__global__ __launch_bounds__(256, 1) void final_kernel(
    const float* __restrict__ hidden, const float* __restrict__ agg_a,
    const float* __restrict__ agg_c,  const float* __restrict__ w3,
    const float* __restrict__ w4,     const float* __restrict__ sv,
    float* __restrict__ out)
{
    extern __shared__ float2 fsm[];
    float2* wq = fsm;                    // [128*128] (w3,w4) interleaved
    float2* hg = wq + 128 * 128;         // [32][128] (h,g)

    const int tid  = threadIdx.x;
    const int lane = tid & 31;
    const int warp = tid >> 5;
    const float s0 = sv[0], s1 = sv[1];

    for (int idx = tid; idx < 128 * 128; idx += 256)
        wq[idx] = make_float2(w3[idx], w4[idx]);

    const int ibase = blockIdx.x * FB_ITEMS;
    for (int idx = tid; idx < FB_ITEMS * 128; idx += 256) {
        const size_t off = (size_t)ibase * 128 + idx;
        hg[idx] = make_float2(hidden[off], s0 * agg_a[off] + s1 * agg_c[off]);
    }
    __syncthreads();

    const int i0 = warp * 4;
    unsigned long long acc[4][4];
    #pragma unroll
    for (int q = 0; q < 4; q++)
        #pragma unroll
        for (int j = 0; j < 4; j++) acc[q][j] = 0ULL;

    #pragma unroll 2
    for (int k = 0; k < 128; k++) {
        const float2* wrow = &wq[k * 128 + lane];
        unsigned long long wv0 = *(const unsigned long long*)&wrow[0];
        unsigned long long wv1 = *(const unsigned long long*)&wrow[32];
        unsigned long long wv2 = *(const unsigned long long*)&wrow[64];
        unsigned long long wv3 = *(const unsigned long long*)&wrow[96];
        #pragma unroll
        for (int q = 0; q < 4; q++) {
            unsigned long long hq = *(const unsigned long long*)&hg[(i0 + q) * 128 + k];
            FMA2(acc[q][0], hq, wv0);
            FMA2(acc[q][1], hq, wv1);
            FMA2(acc[q][2], hq, wv2);
            FMA2(acc[q][3], hq, wv3);
        }
    }
    #pragma unroll
    for (int q = 0; q < 4; q++) {
        const int n = ibase + i0 + q;
        #pragma unroll
        for (int j = 0; j < 4; j++) {
            const int col = lane + 32 * j;
            float a0, a1;
            unpack_f32(acc[q][j], a0, a1);
            const float wgt = 1.f / (1.f + __expf(-(a0 + a1)));
            float2 v = hg[(i0 + q) * 128 + col];
            out[(size_t)n * 128 + col] = (1.f - wgt) * v.x + wgt * v.y;
        }
    }
}

extern "C" void kernel_launch(void* const* d_in, const int* in_sizes, int n_in,
                              void* d_out, int out_size)
{
    const float* hidden = (const float*)d_in[0];
    const float* nh1    = (const float*)d_in[1];
    const float* nh2    = (const float*)d_in[2];
    const float* nw0    = (const float*)d_in[3];
    const float* nw1    = (const float*)d_in[4];
    const float* w1     = (const float*)d_in[5];
    const float* w2     = (const float*)d_in[6];
    const float* w3     = (const float*)d_in[7];
    const float* w4     = (const float*)d_in[8];
    const float* sv     = (const float*)d_in[9];
    float* out = (float*)d_out;

    float *agg_a, *agg_b, *agg_c;
    cudaGetSymbolAddress((void**)&agg_a, g_agg_a);
    cudaGetSymbolAddress((void**)&agg_b, g_agg_b);
    cudaGetSymbolAddress((void**)&agg_c, g_agg_c);

    cudaFuncSetAttribute(fused_agg_kernel,
                         cudaFuncAttributeMaxDynamicSharedMemorySize, SMEM_BYTES);
    cudaFuncSetAttribute(final_kernel,
                         cudaFuncAttributeMaxDynamicSharedMemorySize, FIN_SMEM);

    const int GP = 296;                      // 2 CTAs per SM
    const int T0 = 3200  / ITEMS_PER_TILE;   // 800 tiles
    const int T1 = 38400 / ITEMS_PER_TILE;   // 9600 tiles

    // hop 1: both levels merged (A = big, B = small)
    fused_agg_kernel<<<GP, NTHREADS, SMEM_BYTES>>>(
        nh1, nh2, nw1, agg_b, T1,
        hidden, nh1, nw0, agg_a, T0,
        w1, w2);
    // hop 2
    fused_agg_kernel<<<GP, NTHREADS, SMEM_BYTES>>>(
        agg_a, agg_b, nw0, agg_c, T0,
        agg_a, agg_b, nw0, agg_c, 0,
        w1, w2);
    // gate
    final_kernel<<<100, 256, FIN_SMEM>>>(hidden, agg_a, agg_c, w3, w4, sv, out);
}